// round 11
// baseline (speedup 1.0000x reference)
#include <cuda_runtime.h>
#include <cuda_bf16.h>
#include <stdint.h>

#define BATCH 32
#define NPTS  8192
#define NCLST 64
#define C1    128
#define C2    256
#define CF    512
#define CO    384
#define PTOT  (BATCH*NPTS)
#define NFG   (BATCH*NCLST)
#define ENC_NEG_INF 0x007FFFFFu

#define ROWB   80
#define PLANE  (128*ROWB)       // 10240 B
#define BUFB   (4*PLANE)        // 40960 B
#define KC     32
#define SVSTR  130              // f32 stride of epilogue tile
#define SVB    (128*SVSTR*4)    // 66560 B

// ---------------- scratch ----------------
__device__ unsigned g_fg[NFG*C2];
__device__ unsigned g_om[NFG*CO];
__device__ int g_perm[PTOT];
__device__ int g_chs[PTOT];
__device__ __align__(16) uint16_t g_h_h[(size_t)PTOT*C1];
__device__ __align__(16) uint16_t g_h_l[(size_t)PTOT*C1];
__device__ __align__(16) uint16_t g_feat_h[(size_t)PTOT*C2];
__device__ __align__(16) uint16_t g_feat_l[(size_t)PTOT*C2];
__device__ __align__(16) uint16_t g_fg_h[NFG*C2];
__device__ __align__(16) uint16_t g_fg_l[NFG*C2];
__device__ __align__(16) uint16_t g_h2_h[(size_t)PTOT*CF];
__device__ __align__(16) uint16_t g_h2_l[(size_t)PTOT*CF];
__device__ __align__(16) uint16_t g_w2_h[C2*C1], g_w2_l[C2*C1];
__device__ __align__(16) uint16_t g_w3_h[CF*CF], g_w3_l[CF*CF];
__device__ __align__(16) uint16_t g_w4_h[CO*CF], g_w4_l[CO*CF];
__device__ float g_G[(size_t)NFG*CF];
__device__ float g_s2[CF], g_t2[CF];
__device__ __align__(16) float g_w1f[C1*4];

// ---------------- helpers ----------------
__device__ __forceinline__ unsigned enc(float f){
  unsigned u = __float_as_uint(f);
  return (u & 0x80000000u) ? ~u : (u | 0x80000000u);
}
__device__ __forceinline__ float dec(unsigned u){
  u = (u & 0x80000000u) ? (u & 0x7FFFFFFFu) : ~u;
  return __uint_as_float(u);
}
__device__ __forceinline__ void split2(float v, uint16_t& h, uint16_t& l){
  __nv_bfloat16 bh = __float2bfloat16(v);
  float r = v - __bfloat162float(bh);
  if (!(r == r)) r = 0.f;
  h = __bfloat16_as_ushort(bh);
  l = __bfloat16_as_ushort(__float2bfloat16(r));
}
__device__ __forceinline__ uint32_t smem_u32(const void* p){
  uint32_t a;
  asm("{ .reg .u64 t; cvta.to.shared.u64 t, %1; cvt.u32.u64 %0, t; }" : "=r"(a) : "l"(p));
  return a;
}
__device__ __forceinline__ void cp16(uint32_t dst, const void* src){
  asm volatile("cp.async.cg.shared.global [%0], [%1], 16;" :: "r"(dst), "l"(src));
}
#define CP_COMMIT() asm volatile("cp.async.commit_group;" ::: "memory")
#define CP_WAIT1()  asm volatile("cp.async.wait_group 1;"  ::: "memory")
#define CP_WAIT0()  asm volatile("cp.async.wait_group 0;"  ::: "memory")

__device__ __forceinline__ void ldsm4(uint32_t* r, uint32_t addr){
  asm volatile("ldmatrix.sync.aligned.m8n8.x4.shared.b16 {%0,%1,%2,%3}, [%4];"
    : "=r"(r[0]),"=r"(r[1]),"=r"(r[2]),"=r"(r[3]) : "r"(addr));
}
__device__ __forceinline__ void mma16816(float* c, const uint32_t* a, const uint32_t* b){
  asm volatile("mma.sync.aligned.m16n8k16.row.col.f32.bf16.bf16.f32 "
    "{%0,%1,%2,%3}, {%4,%5,%6,%7}, {%8,%9}, {%0,%1,%2,%3};"
    : "+f"(c[0]),"+f"(c[1]),"+f"(c[2]),"+f"(c[3])
    : "r"(a[0]),"r"(a[1]),"r"(a[2]),"r"(a[3]), "r"(b[0]),"r"(b[1]));
}

struct Frag { float acc[4][4][4]; };

__device__ __forceinline__ void mma_chunk(uint32_t sb, uint32_t aoff, uint32_t boff, Frag& F){
  const uint32_t aAh = sb, aAl = sb + PLANE, aBh = sb + 2*PLANE, aBl = sb + 3*PLANE;
  #pragma unroll
  for (int ks = 0; ks < 2; ks++){
    const uint32_t kb = ks * 32;
    uint32_t a[4][4], bH[2][4], bL[2][4];
    #pragma unroll
    for (int mi=0;mi<4;mi++) ldsm4(a[mi],  aAh + aoff + mi*(16*ROWB) + kb);
    #pragma unroll
    for (int nj=0;nj<2;nj++) ldsm4(bH[nj], aBh + boff + nj*(16*ROWB) + kb);
    #pragma unroll
    for (int mi=0;mi<4;mi++)
      #pragma unroll
      for (int nj=0;nj<2;nj++){
        mma16816(F.acc[mi][nj*2+0], a[mi], &bH[nj][0]);
        mma16816(F.acc[mi][nj*2+1], a[mi], &bH[nj][2]);
      }
    #pragma unroll
    for (int nj=0;nj<2;nj++) ldsm4(bL[nj], aBl + boff + nj*(16*ROWB) + kb);
    #pragma unroll
    for (int mi=0;mi<4;mi++)
      #pragma unroll
      for (int nj=0;nj<2;nj++){
        mma16816(F.acc[mi][nj*2+0], a[mi], &bL[nj][0]);
        mma16816(F.acc[mi][nj*2+1], a[mi], &bL[nj][2]);
      }
    #pragma unroll
    for (int mi=0;mi<4;mi++) ldsm4(a[mi], aAl + aoff + mi*(16*ROWB) + kb);
    #pragma unroll
    for (int mi=0;mi<4;mi++)
      #pragma unroll
      for (int nj=0;nj<2;nj++){
        mma16816(F.acc[mi][nj*2+0], a[mi], &bH[nj][0]);
        mma16816(F.acc[mi][nj*2+1], a[mi], &bH[nj][2]);
      }
  }
}

// double-buffered 128x128 gemm core (linear A reads, B row-stride param)
__device__ __forceinline__ void gemm_core(
    uint32_t sb0, int arow0, const uint16_t* __restrict__ Ah,
    const uint16_t* __restrict__ Al, int astride,
    int ch0, const uint16_t* __restrict__ Bh, const uint16_t* __restrict__ Bl,
    int bstride, int bkoff, int NKC, Frag& F)
{
  const int t = threadIdx.x, lane = t & 31, wid = t >> 5;
  const int wm = (wid & 1)*64, wn = (wid >> 1)*32;
  const uint32_t aoff = (uint32_t)(wm + (lane & 15))*ROWB + ((lane >> 4) & 1)*16;
  const uint32_t boff = (uint32_t)(wn + (lane & 7) + ((lane >> 4) & 1)*8)*ROWB
                      + ((lane >> 3) & 1)*16;

  #pragma unroll
  for (int mi=0;mi<4;mi++)
    #pragma unroll
    for (int ni=0;ni<4;ni++)
      #pragma unroll
      for (int c=0;c<4;c++) F.acc[mi][ni][c] = 0.f;

  #define ISSUE(kc) do { \
    uint32_t sbb = sb0 + ((kc)&1)*BUFB; \
    for (int idx=t; idx<512; idx+=256){ \
      int row = idx >> 2, c = idx & 3; \
      size_t offa = (size_t)(arow0 + row)*astride + (kc)*KC + c*8; \
      size_t offb = (size_t)(ch0 + row)*bstride + bkoff + (kc)*KC + c*8; \
      uint32_t so = (uint32_t)row*ROWB + c*16; \
      cp16(sbb + so,         Ah + offa); \
      cp16(sbb + PLANE + so, Al + offa); \
      cp16(sbb + 2*PLANE + so, Bh + offb); \
      cp16(sbb + 3*PLANE + so, Bl + offb); \
    } \
    CP_COMMIT(); \
  } while(0)

  ISSUE(0);
  for (int kc = 0; kc < NKC; kc++){
    if (kc + 1 < NKC){ ISSUE(kc+1); CP_WAIT1(); }
    else             { CP_WAIT0(); }
    __syncthreads();
    mma_chunk(sb0 + (kc&1)*BUFB, aoff, boff, F);
    __syncthreads();
  }
  #undef ISSUE
}

// =====================================================================
__global__ void k_init(){
  int i = blockIdx.x*blockDim.x + threadIdx.x;
  if (i < NFG*C2) g_fg[i] = ENC_NEG_INF;
  if (i < NFG*CO) g_om[i] = ENC_NEG_INF;
}

__global__ __launch_bounds__(256) void k_sort(const int* __restrict__ choice){
  __shared__ int offs[NCLST];
  __shared__ int hist[NCLST];
  const int t = threadIdx.x, b = blockIdx.x;
  const int base = b*NPTS;
  if (t < NCLST){ hist[t] = 0; }
  __syncthreads();
  for (int i=t; i<NPTS; i+=256) atomicAdd(&hist[choice[base+i]], 1);
  __syncthreads();
  if (t == 0){
    int s = 0;
    for (int c=0;c<NCLST;c++){ offs[c] = s; s += hist[c]; }
  }
  __syncthreads();
  for (int i=t; i<NPTS; i+=256){
    int c = choice[base+i];
    int pos = atomicAdd(&offs[c], 1);
    g_perm[base+pos] = base + i;
    g_chs [base+pos] = c;
  }
}

__global__ void k_prep(
    const float* __restrict__ w1, const float* __restrict__ b1,
    const float* __restrict__ bg1, const float* __restrict__ bb1,
    const float* __restrict__ bm1, const float* __restrict__ bv1,
    const float* __restrict__ w2,
    const float* __restrict__ w3, const float* __restrict__ w4,
    const float* __restrict__ b3,
    const float* __restrict__ bg2, const float* __restrict__ bb2,
    const float* __restrict__ bm2, const float* __restrict__ bv2)
{
  int i = blockIdx.x*blockDim.x + threadIdx.x;
  if (i < CF*CF){ uint16_t h,l; split2(w3[i],h,l); g_w3_h[i]=h; g_w3_l[i]=l; }
  int j = i - CF*CF;
  if (j >= 0 && j < CO*CF){ uint16_t h,l; split2(w4[j],h,l); g_w4_h[j]=h; g_w4_l[j]=l; }
  int k = i - CF*CF - CO*CF;
  if (k >= 0 && k < C2*C1){ uint16_t h,l; split2(w2[k],h,l); g_w2_h[k]=h; g_w2_l[k]=l; }
  int m = i - CF*CF - CO*CF - C2*C1;
  if (m >= 0 && m < CF){
    float s = bg2[m] * rsqrtf(bv2[m] + 1e-5f);
    g_s2[m] = s;
    g_t2[m] = bb2[m] + (b3[m] - bm2[m]) * s;
  }
  int q = i - CF*CF - CO*CF - C2*C1 - CF;
  if (q >= 0 && q < C1){
    float s = bg1[q] * rsqrtf(bv1[q] + 1e-5f);
    g_w1f[q*4+0] = w1[q*3+0]*s;
    g_w1f[q*4+1] = w1[q*3+1]*s;
    g_w1f[q*4+2] = w1[q*3+2]*s;
    g_w1f[q*4+3] = (b1[q] - bm1[q])*s + bb1[q];
  }
}

// precompute h = relu(fold_bn1(xyz)) planes, sorted order. warp per point.
__global__ __launch_bounds__(256) void k_h(const float* __restrict__ xyz){
  const int t = threadIdx.x, lane = t & 31, wid = t >> 5;
  const int pt = blockIdx.x*8 + wid;
  const int pidx = g_perm[pt];
  const float x = xyz[(size_t)pidx*3+0];
  const float y = xyz[(size_t)pidx*3+1];
  const float z = xyz[(size_t)pidx*3+2];
  uint32_t oh[2], ol[2];
  #pragma unroll
  for (int p=0; p<2; p++){
    uint16_t hh[2], hl[2];
    #pragma unroll
    for (int j=0; j<2; j++){
      int k = lane*4 + p*2 + j;
      float4 wf = *(const float4*)(g_w1f + 4*k);
      float h = fmaf(x, wf.x, fmaf(y, wf.y, fmaf(z, wf.z, wf.w)));
      h = fmaxf(h, 0.f);
      split2(h, hh[j], hl[j]);
    }
    oh[p] = (uint32_t)hh[0] | ((uint32_t)hh[1] << 16);
    ol[p] = (uint32_t)hl[0] | ((uint32_t)hl[1] << 16);
  }
  *(uint2*)(g_h_h + (size_t)pt*C1 + lane*4) = make_uint2(oh[0], oh[1]);
  *(uint2*)(g_h_l + (size_t)pt*C1 + lane*4) = make_uint2(ol[0], ol[1]);
}

// =====================================================================
// Stage 1: feat = h @ w2^T + b2; segment-reduced fg max.
// grid (2048). CTA loops both ch tiles -> A re-reads hit L2.
// =====================================================================
__global__ __launch_bounds__(256) void k_stage1(const float* __restrict__ b2)
{
  extern __shared__ char smem[];
  __shared__ int scl[128];

  const int t = threadIdx.x, lane = t & 31, wid = t >> 5;
  const int p0 = blockIdx.x*128, bb = blockIdx.x >> 6;

  for (int i=t; i<128; i+=256) scl[i] = g_chs[p0+i];
  __syncthreads();

  const int wm = (wid & 1)*64, wn = (wid >> 1)*32;
  const int r0 = lane >> 2, cp = (lane & 3)*2;
  float* Sv = (float*)smem;

  for (int ic = 0; ic < C2/128; ic++){
    const int ch0 = ic*128;
    Frag F;
    gemm_core(smem_u32(smem), p0, g_h_h, g_h_l, C1, ch0, g_w2_h, g_w2_l, C1, 0, C1/KC, F);

    #pragma unroll
    for (int mi=0;mi<4;mi++){
      int pa = wm + mi*16 + r0;
      size_t ga = (size_t)(p0 + pa), gb = ga + 8;
      #pragma unroll
      for (int ni=0;ni<4;ni++){
        int chl = wn + ni*8 + cp;
        int ch  = ch0 + chl;
        float b0 = b2[ch], b1v = b2[ch+1];
        float x0 = F.acc[mi][ni][0] + b0, x1 = F.acc[mi][ni][1] + b1v;
        float y0 = F.acc[mi][ni][2] + b0, y1 = F.acc[mi][ni][3] + b1v;
        uint16_t h0,l0,h1,l1;
        split2(x0,h0,l0); split2(x1,h1,l1);
        *(uint32_t*)(g_feat_h + ga*C2 + ch) = (uint32_t)h0 | ((uint32_t)h1<<16);
        *(uint32_t*)(g_feat_l + ga*C2 + ch) = (uint32_t)l0 | ((uint32_t)l1<<16);
        split2(y0,h0,l0); split2(y1,h1,l1);
        *(uint32_t*)(g_feat_h + gb*C2 + ch) = (uint32_t)h0 | ((uint32_t)h1<<16);
        *(uint32_t*)(g_feat_l + gb*C2 + ch) = (uint32_t)l0 | ((uint32_t)l1<<16);
        *(float2*)&Sv[(size_t)pa*SVSTR + chl]     = make_float2(x0, x1);
        *(float2*)&Sv[(size_t)(pa+8)*SVSTR + chl] = make_float2(y0, y1);
      }
    }
    __syncthreads();

    {
      const int ch = t & 127, half = t >> 7;
      int r = half*64;
      int cprev = scl[r];
      float run = __int_as_float(0xff800000);
      unsigned* fgb = &g_fg[(size_t)bb*NCLST*C2 + ch0 + ch];
      for (int i=0;i<64;i++,r++){
        int c = scl[r];
        if (c != cprev){
          atomicMax(&fgb[(size_t)cprev*C2], enc(run));
          run = __int_as_float(0xff800000);
          cprev = c;
        }
        run = fmaxf(run, Sv[(size_t)r*SVSTR + ch]);
      }
      atomicMax(&fgb[(size_t)cprev*C2], enc(run));
    }
    __syncthreads();
  }
}

__global__ void k_fg_split(){
  int i = blockIdx.x*blockDim.x + threadIdx.x;
  if (i < NFG*C2){
    uint16_t h,l; split2(dec(g_fg[i]), h, l);
    g_fg_h[i] = h; g_fg_l[i] = l;
  }
}

// =====================================================================
// Cluster GEMM: G = fg @ w3[:, :256]^T   grid (16, 4)
// =====================================================================
__global__ __launch_bounds__(256) void k_gemmC()
{
  extern __shared__ char smem[];
  const int t = threadIdx.x, lane = t & 31, wid = t >> 5;
  const int r0b = blockIdx.x*128;
  const int ch0 = blockIdx.y*128;

  Frag F;
  gemm_core(smem_u32(smem), r0b, g_fg_h, g_fg_l, C2, ch0, g_w3_h, g_w3_l, CF, 0, C2/KC, F);

  const int wm = (wid & 1)*64, wn = (wid >> 1)*32;
  const int r0 = lane >> 2, cp = (lane & 3)*2;
  #pragma unroll
  for (int mi=0;mi<4;mi++){
    size_t ga = (size_t)(r0b + wm + mi*16 + r0), gb = ga + 8;
    #pragma unroll
    for (int ni=0;ni<4;ni++){
      int ch = ch0 + wn + ni*8 + cp;
      *(float2*)(g_G + ga*CF + ch) = make_float2(F.acc[mi][ni][0], F.acc[mi][ni][1]);
      *(float2*)(g_G + gb*CF + ch) = make_float2(F.acc[mi][ni][2], F.acc[mi][ni][3]);
    }
  }
}

// =====================================================================
// GEMM2 (K=256): h2 = relu(bn2(feat @ w3[:,256:]^T + G[cluster]))
// grid (2048). CTA loops 4 ch tiles.
// =====================================================================
__global__ __launch_bounds__(256) void k_gemm2()
{
  extern __shared__ char smem[];
  __shared__ int scl[128];
  const int t = threadIdx.x, lane = t & 31, wid = t >> 5;
  const int p0 = blockIdx.x*128, bb = blockIdx.x >> 6;

  for (int i=t; i<128; i+=256) scl[i] = g_chs[p0+i];
  __syncthreads();

  const int wm = (wid & 1)*64, wn = (wid >> 1)*32;
  const int r0 = lane >> 2, cp = (lane & 3)*2;

  for (int ic = 0; ic < CF/128; ic++){
    const int ch0 = ic*128;
    Frag F;
    gemm_core(smem_u32(smem), p0, g_feat_h, g_feat_l, C2, ch0, g_w3_h, g_w3_l, CF, C2, C2/KC, F);

    #pragma unroll
    for (int mi=0;mi<4;mi++){
      int pa = wm + mi*16 + r0;
      size_t ga = (size_t)(p0 + pa), gb = ga + 8;
      const float* Ga = &g_G[(size_t)(bb*NCLST + scl[pa])*CF];
      const float* Gb = &g_G[(size_t)(bb*NCLST + scl[pa+8])*CF];
      #pragma unroll
      for (int ni=0;ni<4;ni++){
        int ch = ch0 + wn + ni*8 + cp;
        float s0 = g_s2[ch], s1 = g_s2[ch+1];
        float t0 = g_t2[ch], t1 = g_t2[ch+1];
        float2 gva = *(const float2*)(Ga + ch);
        float2 gvb = *(const float2*)(Gb + ch);
        float x0 = fmaxf(fmaf(F.acc[mi][ni][0] + gva.x, s0, t0), 0.f);
        float x1 = fmaxf(fmaf(F.acc[mi][ni][1] + gva.y, s1, t1), 0.f);
        float y0 = fmaxf(fmaf(F.acc[mi][ni][2] + gvb.x, s0, t0), 0.f);
        float y1 = fmaxf(fmaf(F.acc[mi][ni][3] + gvb.y, s1, t1), 0.f);
        uint16_t h0,l0,h1,l1;
        split2(x0,h0,l0); split2(x1,h1,l1);
        *(uint32_t*)(g_h2_h + ga*CF + ch) = (uint32_t)h0 | ((uint32_t)h1<<16);
        *(uint32_t*)(g_h2_l + ga*CF + ch) = (uint32_t)l0 | ((uint32_t)l1<<16);
        split2(y0,h0,l0); split2(y1,h1,l1);
        *(uint32_t*)(g_h2_h + gb*CF + ch) = (uint32_t)h0 | ((uint32_t)h1<<16);
        *(uint32_t*)(g_h2_l + gb*CF + ch) = (uint32_t)l0 | ((uint32_t)l1<<16);
      }
    }
    __syncthreads();
  }
}

// =====================================================================
// GEMM3: out = h2 @ w4^T + b4 -> segment-reduced cluster max
// grid (2048). CTA loops 3 ch tiles.
// =====================================================================
__global__ __launch_bounds__(256) void k_gemm3(const float* __restrict__ b4)
{
  extern __shared__ char smem[];
  __shared__ int scl[128];
  const int t = threadIdx.x, lane = t & 31, wid = t >> 5;
  const int p0 = blockIdx.x*128, bb = blockIdx.x >> 6;

  for (int i=t; i<128; i+=256) scl[i] = g_chs[p0+i];
  __syncthreads();

  const int wm = (wid & 1)*64, wn = (wid >> 1)*32;
  const int r0 = lane >> 2, cp = (lane & 3)*2;
  float* Sv = (float*)smem;

  for (int ic = 0; ic < CO/128; ic++){
    const int ch0 = ic*128;
    Frag F;
    gemm_core(smem_u32(smem), p0, g_h2_h, g_h2_l, CF, ch0, g_w4_h, g_w4_l, CF, 0, CF/KC, F);

    #pragma unroll
    for (int mi=0;mi<4;mi++){
      int pa = wm + mi*16 + r0;
      #pragma unroll
      for (int ni=0;ni<4;ni++){
        int chl = wn + ni*8 + cp;
        int ch  = ch0 + chl;
        float b0 = b4[ch], b1 = b4[ch+1];
        *(float2*)&Sv[(size_t)pa*SVSTR + chl] =
            make_float2(F.acc[mi][ni][0] + b0, F.acc[mi][ni][1] + b1);
        *(float2*)&Sv[(size_t)(pa+8)*SVSTR + chl] =
            make_float2(F.acc[mi][ni][2] + b0, F.acc[mi][ni][3] + b1);
      }
    }
    __syncthreads();

    {
      const int ch = t & 127, half = t >> 7;
      int r = half*64;
      int cprev = scl[r];
      float run = __int_as_float(0xff800000);
      unsigned* omb = &g_om[(size_t)bb*NCLST*CO + ch0 + ch];
      for (int i=0;i<64;i++,r++){
        int c = scl[r];
        if (c != cprev){
          atomicMax(&omb[(size_t)cprev*CO], enc(run));
          run = __int_as_float(0xff800000);
          cprev = c;
        }
        run = fmaxf(run, Sv[(size_t)r*SVSTR + ch]);
      }
      atomicMax(&omb[(size_t)cprev*CO], enc(run));
    }
    __syncthreads();
  }
}

__global__ void k_final(float* __restrict__ out){
  int i = blockIdx.x*blockDim.x + threadIdx.x;
  if (i < NFG*CO) out[i] = dec(g_om[i]);
}

// =====================================================================
extern "C" void kernel_launch(void* const* d_in, const int* in_sizes, int n_in,
                              void* d_out, int out_size)
{
  const float* xyz    = (const float*)d_in[0];
  const int*   choice = (const int*)  d_in[1];
  const float* w1  = (const float*)d_in[2];
  const float* b1  = (const float*)d_in[3];
  const float* g1  = (const float*)d_in[4];
  const float* bb1 = (const float*)d_in[5];
  const float* m1  = (const float*)d_in[6];
  const float* v1  = (const float*)d_in[7];
  const float* w2  = (const float*)d_in[8];
  const float* b2  = (const float*)d_in[9];
  const float* w3  = (const float*)d_in[10];
  const float* b3  = (const float*)d_in[11];
  const float* g2  = (const float*)d_in[12];
  const float* bb2 = (const float*)d_in[13];
  const float* m2  = (const float*)d_in[14];
  const float* v2  = (const float*)d_in[15];
  const float* w4  = (const float*)d_in[16];
  const float* b4  = (const float*)d_in[17];

  size_t smemg = 2*BUFB;      // 81920 (Sv 66560 fits inside)
  cudaFuncSetAttribute(k_stage1, cudaFuncAttributeMaxDynamicSharedMemorySize, (int)smemg);
  cudaFuncSetAttribute(k_gemmC,  cudaFuncAttributeMaxDynamicSharedMemorySize, (int)smemg);
  cudaFuncSetAttribute(k_gemm2,  cudaFuncAttributeMaxDynamicSharedMemorySize, (int)smemg);
  cudaFuncSetAttribute(k_gemm3,  cudaFuncAttributeMaxDynamicSharedMemorySize, (int)smemg);

  int ntot  = NFG*CO;
  int nprep = CF*CF + CO*CF + C2*C1 + CF + C1;

  k_init    <<<(ntot+255)/256, 256>>>();
  k_sort    <<<BATCH, 256>>>(choice);
  k_prep    <<<(nprep+255)/256, 256>>>(w1,b1,g1,bb1,m1,v1,w2, w3,w4,b3,g2,bb2,m2,v2);
  k_h       <<<PTOT/8, 256>>>(xyz);
  k_stage1  <<<PTOT/128, 256, smemg>>>(b2);
  k_fg_split<<<(NFG*C2+255)/256, 256>>>();
  {
    dim3 gcd(NFG/128, CF/128);    // (16, 4)
    k_gemmC<<<gcd, 256, smemg>>>();
  }
  k_gemm2   <<<PTOT/128, 256, smemg>>>();
  k_gemm3   <<<PTOT/128, 256, smemg>>>(b4);
  k_final   <<<(ntot+255)/256, 256>>>((float*)d_out);
}

// round 12
// speedup vs baseline: 1.0251x; 1.0251x over previous
#include <cuda_runtime.h>
#include <cuda_bf16.h>
#include <stdint.h>

#define BATCH 32
#define NPTS  8192
#define NCLST 64
#define C1    128
#define C2    256
#define CF    512
#define CO    384
#define PTOT  (BATCH*NPTS)
#define NFG   (BATCH*NCLST)
#define ENC_NEG_INF 0x007FFFFFu

#define ROWB   80
#define PLANE  (128*ROWB)       // 10240 B
#define BUFB   (4*PLANE)        // 40960 B
#define KC     32
#define SVSTR  130              // f32 stride of epilogue tile
#define SVB    (128*SVSTR*4)    // 66560 B

// ---------------- scratch ----------------
__device__ unsigned g_fg[NFG*C2];
__device__ unsigned g_om[NFG*CO];
__device__ int g_perm[PTOT];                   // sorted pos -> original idx
__device__ int g_chs[PTOT];                    // cluster id at sorted pos
__device__ __align__(16) uint16_t g_feat_h[(size_t)PTOT*C2];
__device__ __align__(16) uint16_t g_feat_l[(size_t)PTOT*C2];
__device__ __align__(16) uint16_t g_fg_h[NFG*C2];
__device__ __align__(16) uint16_t g_fg_l[NFG*C2];
__device__ __align__(16) uint16_t g_h2_h[(size_t)PTOT*CF];
__device__ __align__(16) uint16_t g_h2_l[(size_t)PTOT*CF];
__device__ __align__(16) uint16_t g_w2_h[C2*C1], g_w2_l[C2*C1];
__device__ __align__(16) uint16_t g_w3_h[CF*CF], g_w3_l[CF*CF];
__device__ __align__(16) uint16_t g_w4_h[CO*CF], g_w4_l[CO*CF];
__device__ float g_G[(size_t)NFG*CF];
__device__ float g_s2[CF], g_t2[CF];
__device__ __align__(16) float g_w1f[C1*4];

// ---------------- helpers ----------------
__device__ __forceinline__ unsigned enc(float f){
  unsigned u = __float_as_uint(f);
  return (u & 0x80000000u) ? ~u : (u | 0x80000000u);
}
__device__ __forceinline__ float dec(unsigned u){
  u = (u & 0x80000000u) ? (u & 0x7FFFFFFFu) : ~u;
  return __uint_as_float(u);
}
__device__ __forceinline__ void split2(float v, uint16_t& h, uint16_t& l){
  __nv_bfloat16 bh = __float2bfloat16(v);
  float r = v - __bfloat162float(bh);
  if (!(r == r)) r = 0.f;
  h = __bfloat16_as_ushort(bh);
  l = __bfloat16_as_ushort(__float2bfloat16(r));
}
__device__ __forceinline__ uint32_t smem_u32(const void* p){
  uint32_t a;
  asm("{ .reg .u64 t; cvta.to.shared.u64 t, %1; cvt.u32.u64 %0, t; }" : "=r"(a) : "l"(p));
  return a;
}
__device__ __forceinline__ void cp16(uint32_t dst, const void* src){
  asm volatile("cp.async.cg.shared.global [%0], [%1], 16;" :: "r"(dst), "l"(src));
}
#define CP_COMMIT() asm volatile("cp.async.commit_group;" ::: "memory")
#define CP_WAIT1()  asm volatile("cp.async.wait_group 1;"  ::: "memory")
#define CP_WAIT0()  asm volatile("cp.async.wait_group 0;"  ::: "memory")

__device__ __forceinline__ void ldsm4(uint32_t* r, uint32_t addr){
  asm volatile("ldmatrix.sync.aligned.m8n8.x4.shared.b16 {%0,%1,%2,%3}, [%4];"
    : "=r"(r[0]),"=r"(r[1]),"=r"(r[2]),"=r"(r[3]) : "r"(addr));
}
__device__ __forceinline__ void mma16816(float* c, const uint32_t* a, const uint32_t* b){
  asm volatile("mma.sync.aligned.m16n8k16.row.col.f32.bf16.bf16.f32 "
    "{%0,%1,%2,%3}, {%4,%5,%6,%7}, {%8,%9}, {%0,%1,%2,%3};"
    : "+f"(c[0]),"+f"(c[1]),"+f"(c[2]),"+f"(c[3])
    : "r"(a[0]),"r"(a[1]),"r"(a[2]),"r"(a[3]), "r"(b[0]),"r"(b[1]));
}

struct Frag { float acc[4][4][4]; };

__device__ __forceinline__ void mma_chunk(uint32_t sb, uint32_t aoff, uint32_t boff, Frag& F){
  const uint32_t aAh = sb, aAl = sb + PLANE, aBh = sb + 2*PLANE, aBl = sb + 3*PLANE;
  #pragma unroll
  for (int ks = 0; ks < 2; ks++){
    const uint32_t kb = ks * 32;
    uint32_t a[4][4], bH[2][4], bL[2][4];
    #pragma unroll
    for (int mi=0;mi<4;mi++) ldsm4(a[mi],  aAh + aoff + mi*(16*ROWB) + kb);
    #pragma unroll
    for (int nj=0;nj<2;nj++) ldsm4(bH[nj], aBh + boff + nj*(16*ROWB) + kb);
    #pragma unroll
    for (int mi=0;mi<4;mi++)
      #pragma unroll
      for (int nj=0;nj<2;nj++){
        mma16816(F.acc[mi][nj*2+0], a[mi], &bH[nj][0]);
        mma16816(F.acc[mi][nj*2+1], a[mi], &bH[nj][2]);
      }
    #pragma unroll
    for (int nj=0;nj<2;nj++) ldsm4(bL[nj], aBl + boff + nj*(16*ROWB) + kb);
    #pragma unroll
    for (int mi=0;mi<4;mi++)
      #pragma unroll
      for (int nj=0;nj<2;nj++){
        mma16816(F.acc[mi][nj*2+0], a[mi], &bL[nj][0]);
        mma16816(F.acc[mi][nj*2+1], a[mi], &bL[nj][2]);
      }
    #pragma unroll
    for (int mi=0;mi<4;mi++) ldsm4(a[mi], aAl + aoff + mi*(16*ROWB) + kb);
    #pragma unroll
    for (int mi=0;mi<4;mi++)
      #pragma unroll
      for (int nj=0;nj<2;nj++){
        mma16816(F.acc[mi][nj*2+0], a[mi], &bH[nj][0]);
        mma16816(F.acc[mi][nj*2+1], a[mi], &bH[nj][2]);
      }
  }
}

// generic double-buffered 128x128 gemm core (linear A reads)
__device__ __forceinline__ void gemm_core(
    uint32_t sb0, int arow0, const uint16_t* __restrict__ Ah,
    const uint16_t* __restrict__ Al, int astride,
    int ch0, const uint16_t* __restrict__ Bh, const uint16_t* __restrict__ Bl,
    int bstride, int bkoff, int NKC, Frag& F)
{
  const int t = threadIdx.x, lane = t & 31, wid = t >> 5;
  const int wm = (wid & 1)*64, wn = (wid >> 1)*32;
  const uint32_t aoff = (uint32_t)(wm + (lane & 15))*ROWB + ((lane >> 4) & 1)*16;
  const uint32_t boff = (uint32_t)(wn + (lane & 7) + ((lane >> 4) & 1)*8)*ROWB
                      + ((lane >> 3) & 1)*16;

  #pragma unroll
  for (int mi=0;mi<4;mi++)
    #pragma unroll
    for (int ni=0;ni<4;ni++)
      #pragma unroll
      for (int c=0;c<4;c++) F.acc[mi][ni][c] = 0.f;

  #define ISSUE(kc) do { \
    uint32_t sbb = sb0 + ((kc)&1)*BUFB; \
    for (int idx=t; idx<512; idx+=256){ \
      int row = idx >> 2, c = idx & 3; \
      size_t offa = (size_t)(arow0 + row)*astride + (kc)*KC + c*8; \
      size_t offb = (size_t)(ch0 + row)*bstride + bkoff + (kc)*KC + c*8; \
      uint32_t so = (uint32_t)row*ROWB + c*16; \
      cp16(sbb + so,         Ah + offa); \
      cp16(sbb + PLANE + so, Al + offa); \
      cp16(sbb + 2*PLANE + so, Bh + offb); \
      cp16(sbb + 3*PLANE + so, Bl + offb); \
    } \
    CP_COMMIT(); \
  } while(0)

  ISSUE(0);
  for (int kc = 0; kc < NKC; kc++){
    if (kc + 1 < NKC){ ISSUE(kc+1); CP_WAIT1(); }
    else             { CP_WAIT0(); }
    __syncthreads();
    mma_chunk(sb0 + (kc&1)*BUFB, aoff, boff, F);
    __syncthreads();
  }
  #undef ISSUE
}

// =====================================================================
// counting sort per batch: 1 CTA / batch
__global__ __launch_bounds__(256) void k_sort(const int* __restrict__ choice){
  __shared__ int offs[NCLST];
  __shared__ int hist[NCLST];
  const int t = threadIdx.x, b = blockIdx.x;
  const int base = b*NPTS;
  if (t < NCLST){ hist[t] = 0; }
  __syncthreads();
  for (int i=t; i<NPTS; i+=256) atomicAdd(&hist[choice[base+i]], 1);
  __syncthreads();
  if (t == 0){
    int s = 0;
    for (int c=0;c<NCLST;c++){ offs[c] = s; s += hist[c]; }
  }
  __syncthreads();
  for (int i=t; i<NPTS; i+=256){
    int c = choice[base+i];
    int pos = atomicAdd(&offs[c], 1);
    g_perm[base+pos] = base + i;
    g_chs [base+pos] = c;
  }
}

// k_prep also performs the max-buffer init (k_init merged in)
__global__ void k_prep(
    const float* __restrict__ w1, const float* __restrict__ b1,
    const float* __restrict__ bg1, const float* __restrict__ bb1,
    const float* __restrict__ bm1, const float* __restrict__ bv1,
    const float* __restrict__ w2,
    const float* __restrict__ w3, const float* __restrict__ w4,
    const float* __restrict__ b3,
    const float* __restrict__ bg2, const float* __restrict__ bb2,
    const float* __restrict__ bm2, const float* __restrict__ bv2)
{
  int i = blockIdx.x*blockDim.x + threadIdx.x;
  if (i < NFG*C2) g_fg[i] = ENC_NEG_INF;
  if (i < NFG*CO) g_om[i] = ENC_NEG_INF;
  if (i < CF*CF){ uint16_t h,l; split2(w3[i],h,l); g_w3_h[i]=h; g_w3_l[i]=l; }
  int j = i - CF*CF;
  if (j >= 0 && j < CO*CF){ uint16_t h,l; split2(w4[j],h,l); g_w4_h[j]=h; g_w4_l[j]=l; }
  int k = i - CF*CF - CO*CF;
  if (k >= 0 && k < C2*C1){ uint16_t h,l; split2(w2[k],h,l); g_w2_h[k]=h; g_w2_l[k]=l; }
  int m = i - CF*CF - CO*CF - C2*C1;
  if (m >= 0 && m < CF){
    float s = bg2[m] * rsqrtf(bv2[m] + 1e-5f);
    g_s2[m] = s;
    g_t2[m] = bb2[m] + (b3[m] - bm2[m]) * s;
  }
  int q = i - CF*CF - CO*CF - C2*C1 - CF;
  if (q >= 0 && q < C1){
    float s = bg1[q] * rsqrtf(bv1[q] + 1e-5f);
    g_w1f[q*4+0] = w1[q*3+0]*s;
    g_w1f[q*4+1] = w1[q*3+1]*s;
    g_w1f[q*4+2] = w1[q*3+2]*s;
    g_w1f[q*4+3] = (b1[q] - bm1[q])*s + bb1[q];
  }
}

// =====================================================================
// Stage 1 (HMMA, sorted points, inline h): feat + segment-reduced fg max
// grid (2048, 2)
// =====================================================================
__global__ __launch_bounds__(256) void k_stage1(
    const float* __restrict__ xyz, const float* __restrict__ b2)
{
  extern __shared__ char smem[];
  __shared__ float sx[128][3];
  __shared__ int   scl[128];
  __shared__ int   sperm[128];
  __shared__ __align__(16) float sw1[C1*4];   // cached folded layer-1 weights

  const int t = threadIdx.x, lane = t & 31, wid = t >> 5;
  const int p0 = blockIdx.x*128, bb = blockIdx.x >> 6;
  const int ch0 = blockIdx.y*128;

  for (int i=t; i<128; i+=256){ scl[i] = g_chs[p0+i]; sperm[i] = g_perm[p0+i]; }
  for (int i=t; i<C1*4; i+=256) sw1[i] = g_w1f[i];
  __syncthreads();
  for (int i=t; i<128*3; i+=256) sx[i/3][i%3] = xyz[(size_t)sperm[i/3]*3 + (i%3)];
  __syncthreads();

  const uint32_t sb = smem_u32(smem);
  uint16_t* pAh = (uint16_t*)smem;
  uint16_t* pAl = (uint16_t*)(smem + PLANE);

  const int wm = (wid & 1)*64, wn = (wid >> 1)*32;
  const uint32_t aoff = (uint32_t)(wm + (lane & 15))*ROWB + ((lane >> 4) & 1)*16;
  const uint32_t boff = (uint32_t)(wn + (lane & 7) + ((lane >> 4) & 1)*8)*ROWB
                      + ((lane >> 3) & 1)*16;

  Frag F;
  #pragma unroll
  for (int mi=0;mi<4;mi++)
    #pragma unroll
    for (int ni=0;ni<4;ni++)
      #pragma unroll
      for (int c=0;c<4;c++) F.acc[mi][ni][c] = 0.f;

  for (int kc=0; kc<4; kc++){
    for (int idx=t; idx<512; idx+=256){
      int row = idx >> 2, c = idx & 3;
      size_t off = (size_t)(ch0+row)*C1 + kc*KC + c*8;
      uint32_t so = (uint32_t)row*ROWB + c*16;
      cp16(sb + 2*PLANE + so, g_w2_h + off);
      cp16(sb + 3*PLANE + so, g_w2_l + off);
    }
    CP_COMMIT();
    for (int idx=t; idx<4096; idx+=256){
      int row = idx >> 5, kp = idx & 31;
      int k = kc*KC + kp;
      float4 wf = *(const float4*)(sw1 + 4*k);
      float h = fmaf(sx[row][0], wf.x, fmaf(sx[row][1], wf.y, fmaf(sx[row][2], wf.z, wf.w)));
      h = fmaxf(h, 0.f);
      uint16_t hh, hl; split2(h, hh, hl);
      uint32_t so = (uint32_t)row*(ROWB/2) + kp;
      pAh[so] = hh; pAl[so] = hl;
    }
    CP_WAIT0();
    __syncthreads();
    mma_chunk(sb, aoff, boff, F);
    __syncthreads();
  }

  // epilogue: write feat (sorted layout) + stage tile in smem
  float* Sv = (float*)smem;
  const int r0 = lane >> 2, cp = (lane & 3)*2;
  #pragma unroll
  for (int mi=0;mi<4;mi++){
    int pa = wm + mi*16 + r0;
    size_t ga = (size_t)(p0 + pa), gb = ga + 8;
    #pragma unroll
    for (int ni=0;ni<4;ni++){
      int chl = wn + ni*8 + cp;
      int ch  = ch0 + chl;
      float b0 = b2[ch], b1v = b2[ch+1];
      float x0 = F.acc[mi][ni][0] + b0, x1 = F.acc[mi][ni][1] + b1v;
      float y0 = F.acc[mi][ni][2] + b0, y1 = F.acc[mi][ni][3] + b1v;
      uint16_t h0,l0,h1,l1;
      split2(x0,h0,l0); split2(x1,h1,l1);
      *(uint32_t*)(g_feat_h + ga*C2 + ch) = (uint32_t)h0 | ((uint32_t)h1<<16);
      *(uint32_t*)(g_feat_l + ga*C2 + ch) = (uint32_t)l0 | ((uint32_t)l1<<16);
      split2(y0,h0,l0); split2(y1,h1,l1);
      *(uint32_t*)(g_feat_h + gb*C2 + ch) = (uint32_t)h0 | ((uint32_t)h1<<16);
      *(uint32_t*)(g_feat_l + gb*C2 + ch) = (uint32_t)l0 | ((uint32_t)l1<<16);
      *(float2*)&Sv[(size_t)pa*SVSTR + chl]     = make_float2(x0, x1);
      *(float2*)&Sv[(size_t)(pa+8)*SVSTR + chl] = make_float2(y0, y1);
    }
  }
  __syncthreads();

  // segment-reduced cluster max: 2 threads per channel walk 64 sorted rows
  {
    const int ch = t & 127, half = t >> 7;
    int r = half*64;
    int cprev = scl[r];
    float run = __int_as_float(0xff800000);
    unsigned* fgb = &g_fg[(size_t)bb*NCLST*C2 + ch0 + ch];
    for (int i=0;i<64;i++,r++){
      int c = scl[r];
      if (c != cprev){
        atomicMax(&fgb[(size_t)cprev*C2], enc(run));
        run = __int_as_float(0xff800000);
        cprev = c;
      }
      run = fmaxf(run, Sv[(size_t)r*SVSTR + ch]);
    }
    atomicMax(&fgb[(size_t)cprev*C2], enc(run));
  }
}

__global__ void k_fg_split(){
  int i = blockIdx.x*blockDim.x + threadIdx.x;
  if (i < NFG*C2){
    uint16_t h,l; split2(dec(g_fg[i]), h, l);
    g_fg_h[i] = h; g_fg_l[i] = l;
  }
}

// =====================================================================
// Cluster GEMM: G = fg @ w3[:, :256]^T   grid (16, 4)
// =====================================================================
__global__ __launch_bounds__(256) void k_gemmC()
{
  extern __shared__ char smem[];
  const int t = threadIdx.x, lane = t & 31, wid = t >> 5;
  const int r0b = blockIdx.x*128;
  const int ch0 = blockIdx.y*128;

  Frag F;
  gemm_core(smem_u32(smem), r0b, g_fg_h, g_fg_l, C2, ch0, g_w3_h, g_w3_l, CF, 0, C2/KC, F);

  const int wm = (wid & 1)*64, wn = (wid >> 1)*32;
  const int r0 = lane >> 2, cp = (lane & 3)*2;
  #pragma unroll
  for (int mi=0;mi<4;mi++){
    size_t ga = (size_t)(r0b + wm + mi*16 + r0), gb = ga + 8;
    #pragma unroll
    for (int ni=0;ni<4;ni++){
      int ch = ch0 + wn + ni*8 + cp;
      *(float2*)(g_G + ga*CF + ch) = make_float2(F.acc[mi][ni][0], F.acc[mi][ni][1]);
      *(float2*)(g_G + gb*CF + ch) = make_float2(F.acc[mi][ni][2], F.acc[mi][ni][3]);
    }
  }
}

// =====================================================================
// GEMM2 (K=256): h2 = relu(bn2(feat @ w3[:,256:]^T + G[cluster]))
// grid (2048, 4)
// =====================================================================
__global__ __launch_bounds__(256) void k_gemm2()
{
  extern __shared__ char smem[];
  __shared__ int scl[128];
  const int t = threadIdx.x, lane = t & 31, wid = t >> 5;
  const int p0 = blockIdx.x*128, bb = blockIdx.x >> 6;
  const int ch0 = blockIdx.y*128;

  for (int i=t; i<128; i+=256) scl[i] = g_chs[p0+i];
  __syncthreads();

  Frag F;
  gemm_core(smem_u32(smem), p0, g_feat_h, g_feat_l, C2, ch0, g_w3_h, g_w3_l, CF, C2, C2/KC, F);

  const int wm = (wid & 1)*64, wn = (wid >> 1)*32;
  const int r0 = lane >> 2, cp = (lane & 3)*2;
  #pragma unroll
  for (int mi=0;mi<4;mi++){
    int pa = wm + mi*16 + r0;
    size_t ga = (size_t)(p0 + pa), gb = ga + 8;
    const float* Ga = &g_G[(size_t)(bb*NCLST + scl[pa])*CF];
    const float* Gb = &g_G[(size_t)(bb*NCLST + scl[pa+8])*CF];
    #pragma unroll
    for (int ni=0;ni<4;ni++){
      int ch = ch0 + wn + ni*8 + cp;
      float s0 = g_s2[ch], s1 = g_s2[ch+1];
      float t0 = g_t2[ch], t1 = g_t2[ch+1];
      float2 gva = *(const float2*)(Ga + ch);
      float2 gvb = *(const float2*)(Gb + ch);
      float x0 = fmaxf(fmaf(F.acc[mi][ni][0] + gva.x, s0, t0), 0.f);
      float x1 = fmaxf(fmaf(F.acc[mi][ni][1] + gva.y, s1, t1), 0.f);
      float y0 = fmaxf(fmaf(F.acc[mi][ni][2] + gvb.x, s0, t0), 0.f);
      float y1 = fmaxf(fmaf(F.acc[mi][ni][3] + gvb.y, s1, t1), 0.f);
      uint16_t h0,l0,h1,l1;
      split2(x0,h0,l0); split2(x1,h1,l1);
      *(uint32_t*)(g_h2_h + ga*CF + ch) = (uint32_t)h0 | ((uint32_t)h1<<16);
      *(uint32_t*)(g_h2_l + ga*CF + ch) = (uint32_t)l0 | ((uint32_t)l1<<16);
      split2(y0,h0,l0); split2(y1,h1,l1);
      *(uint32_t*)(g_h2_h + gb*CF + ch) = (uint32_t)h0 | ((uint32_t)h1<<16);
      *(uint32_t*)(g_h2_l + gb*CF + ch) = (uint32_t)l0 | ((uint32_t)l1<<16);
    }
  }
}

// =====================================================================
// GEMM3: out = h2 @ w4^T + b4 -> segment-reduced cluster max
// grid (2048, 3)
// =====================================================================
__global__ __launch_bounds__(256) void k_gemm3(const float* __restrict__ b4)
{
  extern __shared__ char smem[];
  __shared__ int scl[128];
  const int t = threadIdx.x, lane = t & 31, wid = t >> 5;
  const int p0 = blockIdx.x*128, bb = blockIdx.x >> 6;
  const int ch0 = blockIdx.y*128;

  for (int i=t; i<128; i+=256) scl[i] = g_chs[p0+i];
  __syncthreads();

  Frag F;
  gemm_core(smem_u32(smem), p0, g_h2_h, g_h2_l, CF, ch0, g_w4_h, g_w4_l, CF, 0, CF/KC, F);

  float* Sv = (float*)smem;
  const int wm = (wid & 1)*64, wn = (wid >> 1)*32;
  const int r0 = lane >> 2, cp = (lane & 3)*2;
  #pragma unroll
  for (int mi=0;mi<4;mi++){
    int pa = wm + mi*16 + r0;
    #pragma unroll
    for (int ni=0;ni<4;ni++){
      int chl = wn + ni*8 + cp;
      int ch  = ch0 + chl;
      float b0 = b4[ch], b1 = b4[ch+1];
      *(float2*)&Sv[(size_t)pa*SVSTR + chl] =
          make_float2(F.acc[mi][ni][0] + b0, F.acc[mi][ni][1] + b1);
      *(float2*)&Sv[(size_t)(pa+8)*SVSTR + chl] =
          make_float2(F.acc[mi][ni][2] + b0, F.acc[mi][ni][3] + b1);
    }
  }
  __syncthreads();

  {
    const int ch = t & 127, half = t >> 7;
    int r = half*64;
    int cprev = scl[r];
    float run = __int_as_float(0xff800000);
    unsigned* omb = &g_om[(size_t)bb*NCLST*CO + ch0 + ch];
    for (int i=0;i<64;i++,r++){
      int c = scl[r];
      if (c != cprev){
        atomicMax(&omb[(size_t)cprev*CO], enc(run));
        run = __int_as_float(0xff800000);
        cprev = c;
      }
      run = fmaxf(run, Sv[(size_t)r*SVSTR + ch]);
    }
    atomicMax(&omb[(size_t)cprev*CO], enc(run));
  }
}

__global__ void k_final(float* __restrict__ out){
  int i = blockIdx.x*blockDim.x + threadIdx.x;
  if (i < NFG*CO) out[i] = dec(g_om[i]);
}

// =====================================================================
extern "C" void kernel_launch(void* const* d_in, const int* in_sizes, int n_in,
                              void* d_out, int out_size)
{
  const float* xyz    = (const float*)d_in[0];
  const int*   choice = (const int*)  d_in[1];
  const float* w1  = (const float*)d_in[2];
  const float* b1  = (const float*)d_in[3];
  const float* g1  = (const float*)d_in[4];
  const float* bb1 = (const float*)d_in[5];
  const float* m1  = (const float*)d_in[6];
  const float* v1  = (const float*)d_in[7];
  const float* w2  = (const float*)d_in[8];
  const float* b2  = (const float*)d_in[9];
  const float* w3  = (const float*)d_in[10];
  const float* b3  = (const float*)d_in[11];
  const float* g2  = (const float*)d_in[12];
  const float* bb2 = (const float*)d_in[13];
  const float* m2  = (const float*)d_in[14];
  const float* v2  = (const float*)d_in[15];
  const float* w4  = (const float*)d_in[16];
  const float* b4  = (const float*)d_in[17];

  size_t smem1 = SVB;                      // 66560 (staging 40960 fits inside)
  size_t smemg = 2*BUFB;                   // 81920 (Sv 66560 fits inside)
  cudaFuncSetAttribute(k_stage1, cudaFuncAttributeMaxDynamicSharedMemorySize, (int)smem1);
  cudaFuncSetAttribute(k_gemmC,  cudaFuncAttributeMaxDynamicSharedMemorySize, (int)smemg);
  cudaFuncSetAttribute(k_gemm2,  cudaFuncAttributeMaxDynamicSharedMemorySize, (int)smemg);
  cudaFuncSetAttribute(k_gemm3,  cudaFuncAttributeMaxDynamicSharedMemorySize, (int)smemg);

  // k_prep grid must cover init (NFG*CO) and all weight-split work
  int nprep = NFG*CO;   // 786432 >= CF*CF + ... segments individually

  k_sort    <<<BATCH, 256>>>(choice);
  k_prep    <<<(nprep+255)/256, 256>>>(w1,b1,g1,bb1,m1,v1,w2, w3,w4,b3,g2,bb2,m2,v2);
  {
    dim3 g1d(PTOT/128, C2/128);   // (2048, 2)
    k_stage1<<<g1d, 256, smem1>>>(xyz, b2);
  }
  k_fg_split<<<(NFG*C2+255)/256, 256>>>();
  {
    dim3 gcd(NFG/128, CF/128);    // (16, 4)
    k_gemmC<<<gcd, 256, smemg>>>();
    dim3 g2d(PTOT/128, CF/128);   // (2048, 4)
    k_gemm2<<<g2d, 256, smemg>>>();
    dim3 g3d(PTOT/128, CO/128);   // (2048, 3)
    k_gemm3<<<g3d, 256, smemg>>>(b4);
  }
  k_final   <<<(NFG*CO+255)/256, 256>>>((float*)d_out);
}

// round 13
// speedup vs baseline: 1.2115x; 1.1819x over previous
#include <cuda_runtime.h>
#include <cuda_bf16.h>
#include <cuda_fp16.h>
#include <stdint.h>

#define BATCH 32
#define NPTS  8192
#define NCLST 64
#define C1    128
#define C2    256
#define CF    512
#define CO    384
#define PTOT  (BATCH*NPTS)
#define NFG   (BATCH*NCLST)
#define ENC_NEG_INF 0x007FFFFFu

#define ROWB   80
#define PLANE  (128*ROWB)       // 10240 B
#define BUFB   (4*PLANE)        // 40960 B (bf16 core: Ah,Al,Bh,Bl)
#define BUF3   (3*PLANE)        // 30720 B (fp16 core: A,Bh,Bl)
#define KC     32
#define SVSTR  130
#define SVB    (128*SVSTR*4)    // 66560 B

// ---------------- scratch ----------------
__device__ unsigned g_fg[NFG*C2];
__device__ unsigned g_om[NFG*CO];
__device__ int g_perm[PTOT];
__device__ int g_chs[PTOT];
__device__ __align__(16) uint16_t g_feat_h[(size_t)PTOT*C2];
__device__ __align__(16) uint16_t g_feat_l[(size_t)PTOT*C2];
__device__ __align__(16) uint16_t g_fg_h[NFG*C2];
__device__ __align__(16) uint16_t g_fg_l[NFG*C2];
__device__ __align__(16) uint16_t g_h2f[(size_t)PTOT*CF];    // h2 single fp16
__device__ __align__(16) uint16_t g_w2_h[C2*C1], g_w2_l[C2*C1];
__device__ __align__(16) uint16_t g_w3_h[CF*CF], g_w3_l[CF*CF];
__device__ __align__(16) uint16_t g_w4_h[CO*CF], g_w4_l[CO*CF];   // fp16 split
__device__ float g_G[(size_t)NFG*CF];
__device__ float g_s2[CF], g_t2[CF];
__device__ __align__(16) float g_w1f[C1*4];

// ---------------- helpers ----------------
__device__ __forceinline__ unsigned enc(float f){
  unsigned u = __float_as_uint(f);
  return (u & 0x80000000u) ? ~u : (u | 0x80000000u);
}
__device__ __forceinline__ float dec(unsigned u){
  u = (u & 0x80000000u) ? (u & 0x7FFFFFFFu) : ~u;
  return __uint_as_float(u);
}
__device__ __forceinline__ void split2(float v, uint16_t& h, uint16_t& l){
  __nv_bfloat16 bh = __float2bfloat16(v);
  float r = v - __bfloat162float(bh);
  if (!(r == r)) r = 0.f;
  h = __bfloat16_as_ushort(bh);
  l = __bfloat16_as_ushort(__float2bfloat16(r));
}
__device__ __forceinline__ void split2h(float v, uint16_t& h, uint16_t& l){
  __half hh = __float2half_rn(v);
  float r = v - __half2float(hh);
  if (!(r == r)) r = 0.f;
  h = __half_as_ushort(hh);
  l = __half_as_ushort(__float2half_rn(r));
}
__device__ __forceinline__ uint32_t smem_u32(const void* p){
  uint32_t a;
  asm("{ .reg .u64 t; cvta.to.shared.u64 t, %1; cvt.u32.u64 %0, t; }" : "=r"(a) : "l"(p));
  return a;
}
__device__ __forceinline__ void cp16(uint32_t dst, const void* src){
  asm volatile("cp.async.cg.shared.global [%0], [%1], 16;" :: "r"(dst), "l"(src));
}
#define CP_COMMIT() asm volatile("cp.async.commit_group;" ::: "memory")
#define CP_WAIT1()  asm volatile("cp.async.wait_group 1;"  ::: "memory")
#define CP_WAIT0()  asm volatile("cp.async.wait_group 0;"  ::: "memory")

__device__ __forceinline__ void ldsm4(uint32_t* r, uint32_t addr){
  asm volatile("ldmatrix.sync.aligned.m8n8.x4.shared.b16 {%0,%1,%2,%3}, [%4];"
    : "=r"(r[0]),"=r"(r[1]),"=r"(r[2]),"=r"(r[3]) : "r"(addr));
}
__device__ __forceinline__ void mma16816(float* c, const uint32_t* a, const uint32_t* b){
  asm volatile("mma.sync.aligned.m16n8k16.row.col.f32.bf16.bf16.f32 "
    "{%0,%1,%2,%3}, {%4,%5,%6,%7}, {%8,%9}, {%0,%1,%2,%3};"
    : "+f"(c[0]),"+f"(c[1]),"+f"(c[2]),"+f"(c[3])
    : "r"(a[0]),"r"(a[1]),"r"(a[2]),"r"(a[3]), "r"(b[0]),"r"(b[1]));
}
__device__ __forceinline__ void mma16816h(float* c, const uint32_t* a, const uint32_t* b){
  asm volatile("mma.sync.aligned.m16n8k16.row.col.f32.f16.f16.f32 "
    "{%0,%1,%2,%3}, {%4,%5,%6,%7}, {%8,%9}, {%0,%1,%2,%3};"
    : "+f"(c[0]),"+f"(c[1]),"+f"(c[2]),"+f"(c[3])
    : "r"(a[0]),"r"(a[1]),"r"(a[2]),"r"(a[3]), "r"(b[0]),"r"(b[1]));
}

struct Frag { float acc[4][4][4]; };

// bf16 split-3 chunk (proven)
__device__ __forceinline__ void mma_chunk(uint32_t sb, uint32_t aoff, uint32_t boff, Frag& F){
  const uint32_t aAh = sb, aAl = sb + PLANE, aBh = sb + 2*PLANE, aBl = sb + 3*PLANE;
  #pragma unroll
  for (int ks = 0; ks < 2; ks++){
    const uint32_t kb = ks * 32;
    uint32_t a[4][4], bH[2][4], bL[2][4];
    #pragma unroll
    for (int mi=0;mi<4;mi++) ldsm4(a[mi],  aAh + aoff + mi*(16*ROWB) + kb);
    #pragma unroll
    for (int nj=0;nj<2;nj++) ldsm4(bH[nj], aBh + boff + nj*(16*ROWB) + kb);
    #pragma unroll
    for (int mi=0;mi<4;mi++)
      #pragma unroll
      for (int nj=0;nj<2;nj++){
        mma16816(F.acc[mi][nj*2+0], a[mi], &bH[nj][0]);
        mma16816(F.acc[mi][nj*2+1], a[mi], &bH[nj][2]);
      }
    #pragma unroll
    for (int nj=0;nj<2;nj++) ldsm4(bL[nj], aBl + boff + nj*(16*ROWB) + kb);
    #pragma unroll
    for (int mi=0;mi<4;mi++)
      #pragma unroll
      for (int nj=0;nj<2;nj++){
        mma16816(F.acc[mi][nj*2+0], a[mi], &bL[nj][0]);
        mma16816(F.acc[mi][nj*2+1], a[mi], &bL[nj][2]);
      }
    #pragma unroll
    for (int mi=0;mi<4;mi++) ldsm4(a[mi], aAl + aoff + mi*(16*ROWB) + kb);
    #pragma unroll
    for (int mi=0;mi<4;mi++)
      #pragma unroll
      for (int nj=0;nj<2;nj++){
        mma16816(F.acc[mi][nj*2+0], a[mi], &bH[nj][0]);
        mma16816(F.acc[mi][nj*2+1], a[mi], &bH[nj][2]);
      }
  }
}

// fp16 2-term chunk: A single plane, B split hi/lo
__device__ __forceinline__ void mma_chunk3(uint32_t sb, uint32_t aoff, uint32_t boff, Frag& F){
  const uint32_t aA = sb, aBh = sb + PLANE, aBl = sb + 2*PLANE;
  #pragma unroll
  for (int ks = 0; ks < 2; ks++){
    const uint32_t kb = ks * 32;
    uint32_t a[4][4], bH[2][4], bL[2][4];
    #pragma unroll
    for (int mi=0;mi<4;mi++) ldsm4(a[mi],  aA  + aoff + mi*(16*ROWB) + kb);
    #pragma unroll
    for (int nj=0;nj<2;nj++) ldsm4(bH[nj], aBh + boff + nj*(16*ROWB) + kb);
    #pragma unroll
    for (int mi=0;mi<4;mi++)
      #pragma unroll
      for (int nj=0;nj<2;nj++){
        mma16816h(F.acc[mi][nj*2+0], a[mi], &bH[nj][0]);
        mma16816h(F.acc[mi][nj*2+1], a[mi], &bH[nj][2]);
      }
    #pragma unroll
    for (int nj=0;nj<2;nj++) ldsm4(bL[nj], aBl + boff + nj*(16*ROWB) + kb);
    #pragma unroll
    for (int mi=0;mi<4;mi++)
      #pragma unroll
      for (int nj=0;nj<2;nj++){
        mma16816h(F.acc[mi][nj*2+0], a[mi], &bL[nj][0]);
        mma16816h(F.acc[mi][nj*2+1], a[mi], &bL[nj][2]);
      }
  }
}

// bf16 split-3 double-buffered core
__device__ __forceinline__ void gemm_core(
    uint32_t sb0, int arow0, const uint16_t* __restrict__ Ah,
    const uint16_t* __restrict__ Al, int astride,
    int ch0, const uint16_t* __restrict__ Bh, const uint16_t* __restrict__ Bl,
    int bstride, int bkoff, int NKC, Frag& F)
{
  const int t = threadIdx.x, lane = t & 31, wid = t >> 5;
  const int wm = (wid & 1)*64, wn = (wid >> 1)*32;
  const uint32_t aoff = (uint32_t)(wm + (lane & 15))*ROWB + ((lane >> 4) & 1)*16;
  const uint32_t boff = (uint32_t)(wn + (lane & 7) + ((lane >> 4) & 1)*8)*ROWB
                      + ((lane >> 3) & 1)*16;

  #pragma unroll
  for (int mi=0;mi<4;mi++)
    #pragma unroll
    for (int ni=0;ni<4;ni++)
      #pragma unroll
      for (int c=0;c<4;c++) F.acc[mi][ni][c] = 0.f;

  #define ISSUE(kc) do { \
    uint32_t sbb = sb0 + ((kc)&1)*BUFB; \
    for (int idx=t; idx<512; idx+=256){ \
      int row = idx >> 2, c = idx & 3; \
      size_t offa = (size_t)(arow0 + row)*astride + (kc)*KC + c*8; \
      size_t offb = (size_t)(ch0 + row)*bstride + bkoff + (kc)*KC + c*8; \
      uint32_t so = (uint32_t)row*ROWB + c*16; \
      cp16(sbb + so,         Ah + offa); \
      cp16(sbb + PLANE + so, Al + offa); \
      cp16(sbb + 2*PLANE + so, Bh + offb); \
      cp16(sbb + 3*PLANE + so, Bl + offb); \
    } \
    CP_COMMIT(); \
  } while(0)

  ISSUE(0);
  for (int kc = 0; kc < NKC; kc++){
    if (kc + 1 < NKC){ ISSUE(kc+1); CP_WAIT1(); }
    else             { CP_WAIT0(); }
    __syncthreads();
    mma_chunk(sb0 + (kc&1)*BUFB, aoff, boff, F);
    __syncthreads();
  }
  #undef ISSUE
}

// =====================================================================
__global__ __launch_bounds__(256) void k_sort(const int* __restrict__ choice){
  __shared__ int offs[NCLST];
  __shared__ int hist[NCLST];
  const int t = threadIdx.x, b = blockIdx.x;
  const int base = b*NPTS;
  if (t < NCLST){ hist[t] = 0; }
  __syncthreads();
  for (int i=t; i<NPTS; i+=256) atomicAdd(&hist[choice[base+i]], 1);
  __syncthreads();
  if (t == 0){
    int s = 0;
    for (int c=0;c<NCLST;c++){ offs[c] = s; s += hist[c]; }
  }
  __syncthreads();
  for (int i=t; i<NPTS; i+=256){
    int c = choice[base+i];
    int pos = atomicAdd(&offs[c], 1);
    g_perm[base+pos] = base + i;
    g_chs [base+pos] = c;
  }
}

__global__ void k_prep(
    const float* __restrict__ w1, const float* __restrict__ b1,
    const float* __restrict__ bg1, const float* __restrict__ bb1,
    const float* __restrict__ bm1, const float* __restrict__ bv1,
    const float* __restrict__ w2,
    const float* __restrict__ w3, const float* __restrict__ w4,
    const float* __restrict__ b3,
    const float* __restrict__ bg2, const float* __restrict__ bb2,
    const float* __restrict__ bm2, const float* __restrict__ bv2)
{
  int i = blockIdx.x*blockDim.x + threadIdx.x;
  if (i < NFG*C2) g_fg[i] = ENC_NEG_INF;
  if (i < NFG*CO) g_om[i] = ENC_NEG_INF;
  if (i < CF*CF){ uint16_t h,l; split2(w3[i],h,l); g_w3_h[i]=h; g_w3_l[i]=l; }
  int j = i - CF*CF;
  if (j >= 0 && j < CO*CF){ uint16_t h,l; split2h(w4[j],h,l); g_w4_h[j]=h; g_w4_l[j]=l; }
  int k = i - CF*CF - CO*CF;
  if (k >= 0 && k < C2*C1){ uint16_t h,l; split2(w2[k],h,l); g_w2_h[k]=h; g_w2_l[k]=l; }
  int m = i - CF*CF - CO*CF - C2*C1;
  if (m >= 0 && m < CF){
    float s = bg2[m] * rsqrtf(bv2[m] + 1e-5f);
    g_s2[m] = s;
    g_t2[m] = bb2[m] + (b3[m] - bm2[m]) * s;
  }
  int q = i - CF*CF - CO*CF - C2*C1 - CF;
  if (q >= 0 && q < C1){
    float s = bg1[q] * rsqrtf(bv1[q] + 1e-5f);
    g_w1f[q*4+0] = w1[q*3+0]*s;
    g_w1f[q*4+1] = w1[q*3+1]*s;
    g_w1f[q*4+2] = w1[q*3+2]*s;
    g_w1f[q*4+3] = (b1[q] - bm1[q])*s + bb1[q];
  }
}

// =====================================================================
// Stage 1 (bf16 HMMA, inline h): feat + segment-reduced fg max. grid (2048,2)
// =====================================================================
__global__ __launch_bounds__(256) void k_stage1(
    const float* __restrict__ xyz, const float* __restrict__ b2)
{
  extern __shared__ char smem[];
  __shared__ float sx[128][3];
  __shared__ int   scl[128];
  __shared__ int   sperm[128];
  __shared__ __align__(16) float sw1[C1*4];

  const int t = threadIdx.x, lane = t & 31, wid = t >> 5;
  const int p0 = blockIdx.x*128, bb = blockIdx.x >> 6;
  const int ch0 = blockIdx.y*128;

  for (int i=t; i<128; i+=256){ scl[i] = g_chs[p0+i]; sperm[i] = g_perm[p0+i]; }
  for (int i=t; i<C1*4; i+=256) sw1[i] = g_w1f[i];
  __syncthreads();
  for (int i=t; i<128*3; i+=256) sx[i/3][i%3] = xyz[(size_t)sperm[i/3]*3 + (i%3)];
  __syncthreads();

  const uint32_t sb = smem_u32(smem);
  uint16_t* pAh = (uint16_t*)smem;
  uint16_t* pAl = (uint16_t*)(smem + PLANE);

  const int wm = (wid & 1)*64, wn = (wid >> 1)*32;
  const uint32_t aoff = (uint32_t)(wm + (lane & 15))*ROWB + ((lane >> 4) & 1)*16;
  const uint32_t boff = (uint32_t)(wn + (lane & 7) + ((lane >> 4) & 1)*8)*ROWB
                      + ((lane >> 3) & 1)*16;

  Frag F;
  #pragma unroll
  for (int mi=0;mi<4;mi++)
    #pragma unroll
    for (int ni=0;ni<4;ni++)
      #pragma unroll
      for (int c=0;c<4;c++) F.acc[mi][ni][c] = 0.f;

  for (int kc=0; kc<4; kc++){
    for (int idx=t; idx<512; idx+=256){
      int row = idx >> 2, c = idx & 3;
      size_t off = (size_t)(ch0+row)*C1 + kc*KC + c*8;
      uint32_t so = (uint32_t)row*ROWB + c*16;
      cp16(sb + 2*PLANE + so, g_w2_h + off);
      cp16(sb + 3*PLANE + so, g_w2_l + off);
    }
    CP_COMMIT();
    for (int idx=t; idx<4096; idx+=256){
      int row = idx >> 5, kp = idx & 31;
      int k = kc*KC + kp;
      float4 wf = *(const float4*)(sw1 + 4*k);
      float h = fmaf(sx[row][0], wf.x, fmaf(sx[row][1], wf.y, fmaf(sx[row][2], wf.z, wf.w)));
      h = fmaxf(h, 0.f);
      uint16_t hh, hl; split2(h, hh, hl);
      uint32_t so = (uint32_t)row*(ROWB/2) + kp;
      pAh[so] = hh; pAl[so] = hl;
    }
    CP_WAIT0();
    __syncthreads();
    mma_chunk(sb, aoff, boff, F);
    __syncthreads();
  }

  float* Sv = (float*)smem;
  const int r0 = lane >> 2, cp = (lane & 3)*2;
  #pragma unroll
  for (int mi=0;mi<4;mi++){
    int pa = wm + mi*16 + r0;
    size_t ga = (size_t)(p0 + pa), gb = ga + 8;
    #pragma unroll
    for (int ni=0;ni<4;ni++){
      int chl = wn + ni*8 + cp;
      int ch  = ch0 + chl;
      float b0 = b2[ch], b1v = b2[ch+1];
      float x0 = F.acc[mi][ni][0] + b0, x1 = F.acc[mi][ni][1] + b1v;
      float y0 = F.acc[mi][ni][2] + b0, y1 = F.acc[mi][ni][3] + b1v;
      uint16_t h0,l0,h1,l1;
      split2(x0,h0,l0); split2(x1,h1,l1);
      *(uint32_t*)(g_feat_h + ga*C2 + ch) = (uint32_t)h0 | ((uint32_t)h1<<16);
      *(uint32_t*)(g_feat_l + ga*C2 + ch) = (uint32_t)l0 | ((uint32_t)l1<<16);
      split2(y0,h0,l0); split2(y1,h1,l1);
      *(uint32_t*)(g_feat_h + gb*C2 + ch) = (uint32_t)h0 | ((uint32_t)h1<<16);
      *(uint32_t*)(g_feat_l + gb*C2 + ch) = (uint32_t)l0 | ((uint32_t)l1<<16);
      *(float2*)&Sv[(size_t)pa*SVSTR + chl]     = make_float2(x0, x1);
      *(float2*)&Sv[(size_t)(pa+8)*SVSTR + chl] = make_float2(y0, y1);
    }
  }
  __syncthreads();

  {
    const int ch = t & 127, half = t >> 7;
    int r = half*64;
    int cprev = scl[r];
    float run = __int_as_float(0xff800000);
    unsigned* fgb = &g_fg[(size_t)bb*NCLST*C2 + ch0 + ch];
    for (int i=0;i<64;i++,r++){
      int c = scl[r];
      if (c != cprev){
        atomicMax(&fgb[(size_t)cprev*C2], enc(run));
        run = __int_as_float(0xff800000);
        cprev = c;
      }
      run = fmaxf(run, Sv[(size_t)r*SVSTR + ch]);
    }
    atomicMax(&fgb[(size_t)cprev*C2], enc(run));
  }
}

__global__ void k_fg_split(){
  int i = blockIdx.x*blockDim.x + threadIdx.x;
  if (i < NFG*C2){
    uint16_t h,l; split2(dec(g_fg[i]), h, l);
    g_fg_h[i] = h; g_fg_l[i] = l;
  }
}

// =====================================================================
// Cluster GEMM: G = fg @ w3[:, :256]^T   grid (16, 4)
// =====================================================================
__global__ __launch_bounds__(256) void k_gemmC()
{
  extern __shared__ char smem[];
  const int t = threadIdx.x, lane = t & 31, wid = t >> 5;
  const int r0b = blockIdx.x*128;
  const int ch0 = blockIdx.y*128;

  Frag F;
  gemm_core(smem_u32(smem), r0b, g_fg_h, g_fg_l, C2, ch0, g_w3_h, g_w3_l, CF, 0, C2/KC, F);

  const int wm = (wid & 1)*64, wn = (wid >> 1)*32;
  const int r0 = lane >> 2, cp = (lane & 3)*2;
  #pragma unroll
  for (int mi=0;mi<4;mi++){
    size_t ga = (size_t)(r0b + wm + mi*16 + r0), gb = ga + 8;
    #pragma unroll
    for (int ni=0;ni<4;ni++){
      int ch = ch0 + wn + ni*8 + cp;
      *(float2*)(g_G + ga*CF + ch) = make_float2(F.acc[mi][ni][0], F.acc[mi][ni][1]);
      *(float2*)(g_G + gb*CF + ch) = make_float2(F.acc[mi][ni][2], F.acc[mi][ni][3]);
    }
  }
}

// =====================================================================
// GEMM2 (K=256): h2 = relu(bn2(feat @ w3[:,256:]^T + G[cluster]))
// -> single fp16 plane.  grid (2048, 4)
// =====================================================================
__global__ __launch_bounds__(256) void k_gemm2()
{
  extern __shared__ char smem[];
  __shared__ int scl[128];
  const int t = threadIdx.x, lane = t & 31, wid = t >> 5;
  const int p0 = blockIdx.x*128, bb = blockIdx.x >> 6;
  const int ch0 = blockIdx.y*128;

  for (int i=t; i<128; i+=256) scl[i] = g_chs[p0+i];
  __syncthreads();

  Frag F;
  gemm_core(smem_u32(smem), p0, g_feat_h, g_feat_l, C2, ch0, g_w3_h, g_w3_l, CF, C2, C2/KC, F);

  const int wm = (wid & 1)*64, wn = (wid >> 1)*32;
  const int r0 = lane >> 2, cp = (lane & 3)*2;
  #pragma unroll
  for (int mi=0;mi<4;mi++){
    int pa = wm + mi*16 + r0;
    size_t ga = (size_t)(p0 + pa), gb = ga + 8;
    const float* Ga = &g_G[(size_t)(bb*NCLST + scl[pa])*CF];
    const float* Gb = &g_G[(size_t)(bb*NCLST + scl[pa+8])*CF];
    #pragma unroll
    for (int ni=0;ni<4;ni++){
      int ch = ch0 + wn + ni*8 + cp;
      float s0 = g_s2[ch], s1 = g_s2[ch+1];
      float t0 = g_t2[ch], t1 = g_t2[ch+1];
      float2 gva = *(const float2*)(Ga + ch);
      float2 gvb = *(const float2*)(Gb + ch);
      float x0 = fmaxf(fmaf(F.acc[mi][ni][0] + gva.x, s0, t0), 0.f);
      float x1 = fmaxf(fmaf(F.acc[mi][ni][1] + gva.y, s1, t1), 0.f);
      float y0 = fmaxf(fmaf(F.acc[mi][ni][2] + gvb.x, s0, t0), 0.f);
      float y1 = fmaxf(fmaf(F.acc[mi][ni][3] + gvb.y, s1, t1), 0.f);
      uint32_t px = (uint32_t)__half_as_ushort(__float2half_rn(x0))
                  | ((uint32_t)__half_as_ushort(__float2half_rn(x1)) << 16);
      uint32_t py = (uint32_t)__half_as_ushort(__float2half_rn(y0))
                  | ((uint32_t)__half_as_ushort(__float2half_rn(y1)) << 16);
      *(uint32_t*)(g_h2f + ga*CF + ch) = px;
      *(uint32_t*)(g_h2f + gb*CF + ch) = py;
    }
  }
}

// =====================================================================
// GEMM3 (fp16 2-term): out = h2_f16 @ (w4h+w4l)^T + b4 -> segment max
// grid (2048, 3)
// =====================================================================
__global__ __launch_bounds__(256) void k_gemm3(const float* __restrict__ b4)
{
  extern __shared__ char smem[];
  __shared__ int scl[128];
  const int t = threadIdx.x, lane = t & 31, wid = t >> 5;
  const int p0 = blockIdx.x*128, bb = blockIdx.x >> 6;
  const int ch0 = blockIdx.y*128;

  for (int i=t; i<128; i+=256) scl[i] = g_chs[p0+i];
  __syncthreads();

  const uint32_t sb0 = smem_u32(smem);
  const int wm = (wid & 1)*64, wn = (wid >> 1)*32;
  const uint32_t aoff = (uint32_t)(wm + (lane & 15))*ROWB + ((lane >> 4) & 1)*16;
  const uint32_t boff = (uint32_t)(wn + (lane & 7) + ((lane >> 4) & 1)*8)*ROWB
                      + ((lane >> 3) & 1)*16;

  Frag F;
  #pragma unroll
  for (int mi=0;mi<4;mi++)
    #pragma unroll
    for (int ni=0;ni<4;ni++)
      #pragma unroll
      for (int c=0;c<4;c++) F.acc[mi][ni][c] = 0.f;

  #define ISSUE3(kc) do { \
    uint32_t sbb = sb0 + ((kc)&1)*BUF3; \
    for (int idx=t; idx<512; idx+=256){ \
      int row = idx >> 2, c = idx & 3; \
      size_t offa = (size_t)(p0 + row)*CF + (kc)*KC + c*8; \
      size_t offb = (size_t)(ch0 + row)*CF + (kc)*KC + c*8; \
      uint32_t so = (uint32_t)row*ROWB + c*16; \
      cp16(sbb + so,           g_h2f + offa); \
      cp16(sbb + PLANE + so,   g_w4_h + offb); \
      cp16(sbb + 2*PLANE + so, g_w4_l + offb); \
    } \
    CP_COMMIT(); \
  } while(0)

  ISSUE3(0);
  const int NKC = CF/KC;   // 16
  for (int kc = 0; kc < NKC; kc++){
    if (kc + 1 < NKC){ ISSUE3(kc+1); CP_WAIT1(); }
    else             { CP_WAIT0(); }
    __syncthreads();
    mma_chunk3(sb0 + (kc&1)*BUF3, aoff, boff, F);
    __syncthreads();
  }
  #undef ISSUE3

  float* Sv = (float*)smem;
  const int r0 = lane >> 2, cp = (lane & 3)*2;
  #pragma unroll
  for (int mi=0;mi<4;mi++){
    int pa = wm + mi*16 + r0;
    #pragma unroll
    for (int ni=0;ni<4;ni++){
      int chl = wn + ni*8 + cp;
      int ch  = ch0 + chl;
      float b0 = b4[ch], b1 = b4[ch+1];
      *(float2*)&Sv[(size_t)pa*SVSTR + chl] =
          make_float2(F.acc[mi][ni][0] + b0, F.acc[mi][ni][1] + b1);
      *(float2*)&Sv[(size_t)(pa+8)*SVSTR + chl] =
          make_float2(F.acc[mi][ni][2] + b0, F.acc[mi][ni][3] + b1);
    }
  }
  __syncthreads();

  {
    const int ch = t & 127, half = t >> 7;
    int r = half*64;
    int cprev = scl[r];
    float run = __int_as_float(0xff800000);
    unsigned* omb = &g_om[(size_t)bb*NCLST*CO + ch0 + ch];
    for (int i=0;i<64;i++,r++){
      int c = scl[r];
      if (c != cprev){
        atomicMax(&omb[(size_t)cprev*CO], enc(run));
        run = __int_as_float(0xff800000);
        cprev = c;
      }
      run = fmaxf(run, Sv[(size_t)r*SVSTR + ch]);
    }
    atomicMax(&omb[(size_t)cprev*CO], enc(run));
  }
}

__global__ void k_final(float* __restrict__ out){
  int i = blockIdx.x*blockDim.x + threadIdx.x;
  if (i < NFG*CO) out[i] = dec(g_om[i]);
}

// =====================================================================
extern "C" void kernel_launch(void* const* d_in, const int* in_sizes, int n_in,
                              void* d_out, int out_size)
{
  const float* xyz    = (const float*)d_in[0];
  const int*   choice = (const int*)  d_in[1];
  const float* w1  = (const float*)d_in[2];
  const float* b1  = (const float*)d_in[3];
  const float* g1  = (const float*)d_in[4];
  const float* bb1 = (const float*)d_in[5];
  const float* m1  = (const float*)d_in[6];
  const float* v1  = (const float*)d_in[7];
  const float* w2  = (const float*)d_in[8];
  const float* b2  = (const float*)d_in[9];
  const float* w3  = (const float*)d_in[10];
  const float* b3  = (const float*)d_in[11];
  const float* g2  = (const float*)d_in[12];
  const float* bb2 = (const float*)d_in[13];
  const float* m2  = (const float*)d_in[14];
  const float* v2  = (const float*)d_in[15];
  const float* w4  = (const float*)d_in[16];
  const float* b4  = (const float*)d_in[17];

  size_t smem1 = SVB;       // 66560
  size_t smemg = 2*BUFB;    // 81920
  size_t smem3 = SVB;       // 66560 (2*BUF3=61440 and Sv=66560 both fit)
  cudaFuncSetAttribute(k_stage1, cudaFuncAttributeMaxDynamicSharedMemorySize, (int)smem1);
  cudaFuncSetAttribute(k_gemmC,  cudaFuncAttributeMaxDynamicSharedMemorySize, (int)smemg);
  cudaFuncSetAttribute(k_gemm2,  cudaFuncAttributeMaxDynamicSharedMemorySize, (int)smemg);
  cudaFuncSetAttribute(k_gemm3,  cudaFuncAttributeMaxDynamicSharedMemorySize, (int)smem3);

  int nprep = NFG*CO;

  k_sort    <<<BATCH, 256>>>(choice);
  k_prep    <<<(nprep+255)/256, 256>>>(w1,b1,g1,bb1,m1,v1,w2, w3,w4,b3,g2,bb2,m2,v2);
  {
    dim3 g1d(PTOT/128, C2/128);   // (2048, 2)
    k_stage1<<<g1d, 256, smem1>>>(xyz, b2);
  }
  k_fg_split<<<(NFG*C2+255)/256, 256>>>();
  {
    dim3 gcd(NFG/128, CF/128);    // (16, 4)
    k_gemmC<<<gcd, 256, smemg>>>();
    dim3 g2d(PTOT/128, CF/128);   // (2048, 4)
    k_gemm2<<<g2d, 256, smemg>>>();
    dim3 g3d(PTOT/128, CO/128);   // (2048, 3)
    k_gemm3<<<g3d, 256, smem3>>>(b4);
  }
  k_final   <<<(NFG*CO+255)/256, 256>>>((float*)d_out);
}

// round 14
// speedup vs baseline: 1.3930x; 1.1498x over previous
#include <cuda_runtime.h>
#include <cuda_bf16.h>
#include <cuda_fp16.h>
#include <stdint.h>

#define BATCH 32
#define NPTS  8192
#define NCLST 64
#define C1    128
#define C2    256
#define CF    512
#define CO    384
#define PTOT  (BATCH*NPTS)
#define NFG   (BATCH*NCLST)
#define ENC_NEG_INF 0x007FFFFFu

#define ROWB   80
#define PLANE  (128*ROWB)       // 10240 B
#define BUFB   (4*PLANE)        // 40960 B (bf16 core: Ah,Al,Bh,Bl)
#define BUF3   (3*PLANE)        // 30720 B (fp16 core: A,Bh,Bl)
#define KC     32
#define SVSTR  130
#define SVB    (128*SVSTR*4)    // 66560 B

// ---------------- scratch ----------------
__device__ unsigned g_fg[NFG*C2];
__device__ unsigned g_om[NFG*CO];
__device__ int g_perm[PTOT];
__device__ int g_chs[PTOT];
__device__ __align__(16) uint16_t g_featf[(size_t)PTOT*C2];  // feat single fp16
__device__ __align__(16) uint16_t g_fgf[NFG*C2];             // fg single fp16
__device__ __align__(16) uint16_t g_h2f[(size_t)PTOT*CF];    // h2 single fp16
__device__ __align__(16) uint16_t g_w2_h[C2*C1], g_w2_l[C2*C1];   // bf16 split
__device__ __align__(16) uint16_t g_w3_h[CF*CF], g_w3_l[CF*CF];   // fp16 split
__device__ __align__(16) uint16_t g_w4_h[CO*CF], g_w4_l[CO*CF];   // fp16 split
__device__ float g_G[(size_t)NFG*CF];
__device__ float g_s2[CF], g_t2[CF];
__device__ __align__(16) float g_w1f[C1*4];

// ---------------- helpers ----------------
__device__ __forceinline__ unsigned enc(float f){
  unsigned u = __float_as_uint(f);
  return (u & 0x80000000u) ? ~u : (u | 0x80000000u);
}
__device__ __forceinline__ float dec(unsigned u){
  u = (u & 0x80000000u) ? (u & 0x7FFFFFFFu) : ~u;
  return __uint_as_float(u);
}
__device__ __forceinline__ void split2(float v, uint16_t& h, uint16_t& l){
  __nv_bfloat16 bh = __float2bfloat16(v);
  float r = v - __bfloat162float(bh);
  if (!(r == r)) r = 0.f;
  h = __bfloat16_as_ushort(bh);
  l = __bfloat16_as_ushort(__float2bfloat16(r));
}
__device__ __forceinline__ void split2h(float v, uint16_t& h, uint16_t& l){
  __half hh = __float2half_rn(v);
  float r = v - __half2float(hh);
  if (!(r == r)) r = 0.f;
  h = __half_as_ushort(hh);
  l = __half_as_ushort(__float2half_rn(r));
}
__device__ __forceinline__ uint32_t smem_u32(const void* p){
  uint32_t a;
  asm("{ .reg .u64 t; cvta.to.shared.u64 t, %1; cvt.u32.u64 %0, t; }" : "=r"(a) : "l"(p));
  return a;
}
__device__ __forceinline__ void cp16(uint32_t dst, const void* src){
  asm volatile("cp.async.cg.shared.global [%0], [%1], 16;" :: "r"(dst), "l"(src));
}
#define CP_COMMIT() asm volatile("cp.async.commit_group;" ::: "memory")
#define CP_WAIT1()  asm volatile("cp.async.wait_group 1;"  ::: "memory")
#define CP_WAIT0()  asm volatile("cp.async.wait_group 0;"  ::: "memory")

__device__ __forceinline__ void ldsm4(uint32_t* r, uint32_t addr){
  asm volatile("ldmatrix.sync.aligned.m8n8.x4.shared.b16 {%0,%1,%2,%3}, [%4];"
    : "=r"(r[0]),"=r"(r[1]),"=r"(r[2]),"=r"(r[3]) : "r"(addr));
}
__device__ __forceinline__ void mma16816(float* c, const uint32_t* a, const uint32_t* b){
  asm volatile("mma.sync.aligned.m16n8k16.row.col.f32.bf16.bf16.f32 "
    "{%0,%1,%2,%3}, {%4,%5,%6,%7}, {%8,%9}, {%0,%1,%2,%3};"
    : "+f"(c[0]),"+f"(c[1]),"+f"(c[2]),"+f"(c[3])
    : "r"(a[0]),"r"(a[1]),"r"(a[2]),"r"(a[3]), "r"(b[0]),"r"(b[1]));
}
__device__ __forceinline__ void mma16816h(float* c, const uint32_t* a, const uint32_t* b){
  asm volatile("mma.sync.aligned.m16n8k16.row.col.f32.f16.f16.f32 "
    "{%0,%1,%2,%3}, {%4,%5,%6,%7}, {%8,%9}, {%0,%1,%2,%3};"
    : "+f"(c[0]),"+f"(c[1]),"+f"(c[2]),"+f"(c[3])
    : "r"(a[0]),"r"(a[1]),"r"(a[2]),"r"(a[3]), "r"(b[0]),"r"(b[1]));
}

struct Frag { float acc[4][4][4]; };

// bf16 split-3 chunk (stage1 only)
__device__ __forceinline__ void mma_chunk(uint32_t sb, uint32_t aoff, uint32_t boff, Frag& F){
  const uint32_t aAh = sb, aAl = sb + PLANE, aBh = sb + 2*PLANE, aBl = sb + 3*PLANE;
  #pragma unroll
  for (int ks = 0; ks < 2; ks++){
    const uint32_t kb = ks * 32;
    uint32_t a[4][4], bH[2][4], bL[2][4];
    #pragma unroll
    for (int mi=0;mi<4;mi++) ldsm4(a[mi],  aAh + aoff + mi*(16*ROWB) + kb);
    #pragma unroll
    for (int nj=0;nj<2;nj++) ldsm4(bH[nj], aBh + boff + nj*(16*ROWB) + kb);
    #pragma unroll
    for (int mi=0;mi<4;mi++)
      #pragma unroll
      for (int nj=0;nj<2;nj++){
        mma16816(F.acc[mi][nj*2+0], a[mi], &bH[nj][0]);
        mma16816(F.acc[mi][nj*2+1], a[mi], &bH[nj][2]);
      }
    #pragma unroll
    for (int nj=0;nj<2;nj++) ldsm4(bL[nj], aBl + boff + nj*(16*ROWB) + kb);
    #pragma unroll
    for (int mi=0;mi<4;mi++)
      #pragma unroll
      for (int nj=0;nj<2;nj++){
        mma16816(F.acc[mi][nj*2+0], a[mi], &bL[nj][0]);
        mma16816(F.acc[mi][nj*2+1], a[mi], &bL[nj][2]);
      }
    #pragma unroll
    for (int mi=0;mi<4;mi++) ldsm4(a[mi], aAl + aoff + mi*(16*ROWB) + kb);
    #pragma unroll
    for (int mi=0;mi<4;mi++)
      #pragma unroll
      for (int nj=0;nj<2;nj++){
        mma16816(F.acc[mi][nj*2+0], a[mi], &bH[nj][0]);
        mma16816(F.acc[mi][nj*2+1], a[mi], &bH[nj][2]);
      }
  }
}

// fp16 2-term chunk: A single plane, B split hi/lo
__device__ __forceinline__ void mma_chunk3(uint32_t sb, uint32_t aoff, uint32_t boff, Frag& F){
  const uint32_t aA = sb, aBh = sb + PLANE, aBl = sb + 2*PLANE;
  #pragma unroll
  for (int ks = 0; ks < 2; ks++){
    const uint32_t kb = ks * 32;
    uint32_t a[4][4], bH[2][4], bL[2][4];
    #pragma unroll
    for (int mi=0;mi<4;mi++) ldsm4(a[mi],  aA  + aoff + mi*(16*ROWB) + kb);
    #pragma unroll
    for (int nj=0;nj<2;nj++) ldsm4(bH[nj], aBh + boff + nj*(16*ROWB) + kb);
    #pragma unroll
    for (int mi=0;mi<4;mi++)
      #pragma unroll
      for (int nj=0;nj<2;nj++){
        mma16816h(F.acc[mi][nj*2+0], a[mi], &bH[nj][0]);
        mma16816h(F.acc[mi][nj*2+1], a[mi], &bH[nj][2]);
      }
    #pragma unroll
    for (int nj=0;nj<2;nj++) ldsm4(bL[nj], aBl + boff + nj*(16*ROWB) + kb);
    #pragma unroll
    for (int mi=0;mi<4;mi++)
      #pragma unroll
      for (int nj=0;nj<2;nj++){
        mma16816h(F.acc[mi][nj*2+0], a[mi], &bL[nj][0]);
        mma16816h(F.acc[mi][nj*2+1], a[mi], &bL[nj][2]);
      }
  }
}

// fp16 2-term double-buffered core (A single plane, B split)
__device__ __forceinline__ void gemm_core3(
    uint32_t sb0, int arow0, const uint16_t* __restrict__ Af, int astride,
    int ch0, const uint16_t* __restrict__ Bh, const uint16_t* __restrict__ Bl,
    int bstride, int bkoff, int NKC, Frag& F)
{
  const int t = threadIdx.x, lane = t & 31, wid = t >> 5;
  const int wm = (wid & 1)*64, wn = (wid >> 1)*32;
  const uint32_t aoff = (uint32_t)(wm + (lane & 15))*ROWB + ((lane >> 4) & 1)*16;
  const uint32_t boff = (uint32_t)(wn + (lane & 7) + ((lane >> 4) & 1)*8)*ROWB
                      + ((lane >> 3) & 1)*16;

  #pragma unroll
  for (int mi=0;mi<4;mi++)
    #pragma unroll
    for (int ni=0;ni<4;ni++)
      #pragma unroll
      for (int c=0;c<4;c++) F.acc[mi][ni][c] = 0.f;

  #define ISSUE3(kc) do { \
    uint32_t sbb = sb0 + ((kc)&1)*BUF3; \
    for (int idx=t; idx<512; idx+=256){ \
      int row = idx >> 2, c = idx & 3; \
      size_t offa = (size_t)(arow0 + row)*astride + (kc)*KC + c*8; \
      size_t offb = (size_t)(ch0 + row)*bstride + bkoff + (kc)*KC + c*8; \
      uint32_t so = (uint32_t)row*ROWB + c*16; \
      cp16(sbb + so,           Af + offa); \
      cp16(sbb + PLANE + so,   Bh + offb); \
      cp16(sbb + 2*PLANE + so, Bl + offb); \
    } \
    CP_COMMIT(); \
  } while(0)

  ISSUE3(0);
  for (int kc = 0; kc < NKC; kc++){
    if (kc + 1 < NKC){ ISSUE3(kc+1); CP_WAIT1(); }
    else             { CP_WAIT0(); }
    __syncthreads();
    mma_chunk3(sb0 + (kc&1)*BUF3, aoff, boff, F);
    __syncthreads();
  }
  #undef ISSUE3
}

// =====================================================================
__global__ __launch_bounds__(256) void k_sort(const int* __restrict__ choice){
  __shared__ int offs[NCLST];
  __shared__ int hist[NCLST];
  const int t = threadIdx.x, b = blockIdx.x;
  const int base = b*NPTS;
  if (t < NCLST){ hist[t] = 0; }
  __syncthreads();
  for (int i=t; i<NPTS; i+=256) atomicAdd(&hist[choice[base+i]], 1);
  __syncthreads();
  if (t == 0){
    int s = 0;
    for (int c=0;c<NCLST;c++){ offs[c] = s; s += hist[c]; }
  }
  __syncthreads();
  for (int i=t; i<NPTS; i+=256){
    int c = choice[base+i];
    int pos = atomicAdd(&offs[c], 1);
    g_perm[base+pos] = base + i;
    g_chs [base+pos] = c;
  }
}

__global__ void k_prep(
    const float* __restrict__ w1, const float* __restrict__ b1,
    const float* __restrict__ bg1, const float* __restrict__ bb1,
    const float* __restrict__ bm1, const float* __restrict__ bv1,
    const float* __restrict__ w2,
    const float* __restrict__ w3, const float* __restrict__ w4,
    const float* __restrict__ b3,
    const float* __restrict__ bg2, const float* __restrict__ bb2,
    const float* __restrict__ bm2, const float* __restrict__ bv2)
{
  int i = blockIdx.x*blockDim.x + threadIdx.x;
  if (i < NFG*C2) g_fg[i] = ENC_NEG_INF;
  if (i < NFG*CO) g_om[i] = ENC_NEG_INF;
  if (i < CF*CF){ uint16_t h,l; split2h(w3[i],h,l); g_w3_h[i]=h; g_w3_l[i]=l; }
  int j = i - CF*CF;
  if (j >= 0 && j < CO*CF){ uint16_t h,l; split2h(w4[j],h,l); g_w4_h[j]=h; g_w4_l[j]=l; }
  int k = i - CF*CF - CO*CF;
  if (k >= 0 && k < C2*C1){ uint16_t h,l; split2(w2[k],h,l); g_w2_h[k]=h; g_w2_l[k]=l; }
  int m = i - CF*CF - CO*CF - C2*C1;
  if (m >= 0 && m < CF){
    float s = bg2[m] * rsqrtf(bv2[m] + 1e-5f);
    g_s2[m] = s;
    g_t2[m] = bb2[m] + (b3[m] - bm2[m]) * s;
  }
  int q = i - CF*CF - CO*CF - C2*C1 - CF;
  if (q >= 0 && q < C1){
    float s = bg1[q] * rsqrtf(bv1[q] + 1e-5f);
    g_w1f[q*4+0] = w1[q*3+0]*s;
    g_w1f[q*4+1] = w1[q*3+1]*s;
    g_w1f[q*4+2] = w1[q*3+2]*s;
    g_w1f[q*4+3] = (b1[q] - bm1[q])*s + bb1[q];
  }
}

// =====================================================================
// Stage 1 (bf16 HMMA, inline h): feat fp16 + segment fg max. grid (2048,2)
// =====================================================================
__global__ __launch_bounds__(256) void k_stage1(
    const float* __restrict__ xyz, const float* __restrict__ b2)
{
  extern __shared__ char smem[];
  __shared__ float sx[128][3];
  __shared__ int   scl[128];
  __shared__ int   sperm[128];
  __shared__ __align__(16) float sw1[C1*4];

  const int t = threadIdx.x, lane = t & 31, wid = t >> 5;
  const int p0 = blockIdx.x*128, bb = blockIdx.x >> 6;
  const int ch0 = blockIdx.y*128;

  for (int i=t; i<128; i+=256){ scl[i] = g_chs[p0+i]; sperm[i] = g_perm[p0+i]; }
  for (int i=t; i<C1*4; i+=256) sw1[i] = g_w1f[i];
  __syncthreads();
  for (int i=t; i<128*3; i+=256) sx[i/3][i%3] = xyz[(size_t)sperm[i/3]*3 + (i%3)];
  __syncthreads();

  const uint32_t sb = smem_u32(smem);
  uint16_t* pAh = (uint16_t*)smem;
  uint16_t* pAl = (uint16_t*)(smem + PLANE);

  const int wm = (wid & 1)*64, wn = (wid >> 1)*32;
  const uint32_t aoff = (uint32_t)(wm + (lane & 15))*ROWB + ((lane >> 4) & 1)*16;
  const uint32_t boff = (uint32_t)(wn + (lane & 7) + ((lane >> 4) & 1)*8)*ROWB
                      + ((lane >> 3) & 1)*16;

  Frag F;
  #pragma unroll
  for (int mi=0;mi<4;mi++)
    #pragma unroll
    for (int ni=0;ni<4;ni++)
      #pragma unroll
      for (int c=0;c<4;c++) F.acc[mi][ni][c] = 0.f;

  for (int kc=0; kc<4; kc++){
    for (int idx=t; idx<512; idx+=256){
      int row = idx >> 2, c = idx & 3;
      size_t off = (size_t)(ch0+row)*C1 + kc*KC + c*8;
      uint32_t so = (uint32_t)row*ROWB + c*16;
      cp16(sb + 2*PLANE + so, g_w2_h + off);
      cp16(sb + 3*PLANE + so, g_w2_l + off);
    }
    CP_COMMIT();
    for (int idx=t; idx<4096; idx+=256){
      int row = idx >> 5, kp = idx & 31;
      int k = kc*KC + kp;
      float4 wf = *(const float4*)(sw1 + 4*k);
      float h = fmaf(sx[row][0], wf.x, fmaf(sx[row][1], wf.y, fmaf(sx[row][2], wf.z, wf.w)));
      h = fmaxf(h, 0.f);
      uint16_t hh, hl; split2(h, hh, hl);
      uint32_t so = (uint32_t)row*(ROWB/2) + kp;
      pAh[so] = hh; pAl[so] = hl;
    }
    CP_WAIT0();
    __syncthreads();
    mma_chunk(sb, aoff, boff, F);
    __syncthreads();
  }

  float* Sv = (float*)smem;
  const int r0 = lane >> 2, cp = (lane & 3)*2;
  #pragma unroll
  for (int mi=0;mi<4;mi++){
    int pa = wm + mi*16 + r0;
    size_t ga = (size_t)(p0 + pa), gb = ga + 8;
    #pragma unroll
    for (int ni=0;ni<4;ni++){
      int chl = wn + ni*8 + cp;
      int ch  = ch0 + chl;
      float b0 = b2[ch], b1v = b2[ch+1];
      // fp16 rounding applied BEFORE the fg max so fg == max over stored feat
      float x0 = __half2float(__float2half_rn(F.acc[mi][ni][0] + b0));
      float x1 = __half2float(__float2half_rn(F.acc[mi][ni][1] + b1v));
      float y0 = __half2float(__float2half_rn(F.acc[mi][ni][2] + b0));
      float y1 = __half2float(__float2half_rn(F.acc[mi][ni][3] + b1v));
      uint32_t px = (uint32_t)__half_as_ushort(__float2half_rn(x0))
                  | ((uint32_t)__half_as_ushort(__float2half_rn(x1)) << 16);
      uint32_t py = (uint32_t)__half_as_ushort(__float2half_rn(y0))
                  | ((uint32_t)__half_as_ushort(__float2half_rn(y1)) << 16);
      *(uint32_t*)(g_featf + ga*C2 + ch) = px;
      *(uint32_t*)(g_featf + gb*C2 + ch) = py;
      *(float2*)&Sv[(size_t)pa*SVSTR + chl]     = make_float2(x0, x1);
      *(float2*)&Sv[(size_t)(pa+8)*SVSTR + chl] = make_float2(y0, y1);
    }
  }
  __syncthreads();

  {
    const int ch = t & 127, half = t >> 7;
    int r = half*64;
    int cprev = scl[r];
    float run = __int_as_float(0xff800000);
    unsigned* fgb = &g_fg[(size_t)bb*NCLST*C2 + ch0 + ch];
    for (int i=0;i<64;i++,r++){
      int c = scl[r];
      if (c != cprev){
        atomicMax(&fgb[(size_t)cprev*C2], enc(run));
        run = __int_as_float(0xff800000);
        cprev = c;
      }
      run = fmaxf(run, Sv[(size_t)r*SVSTR + ch]);
    }
    atomicMax(&fgb[(size_t)cprev*C2], enc(run));
  }
}

__global__ void k_fg_split(){
  int i = blockIdx.x*blockDim.x + threadIdx.x;
  if (i < NFG*C2)
    g_fgf[i] = __half_as_ushort(__float2half_rn(dec(g_fg[i])));
}

// =====================================================================
// Cluster GEMM (fp16 2-term): G = fg @ w3[:, :256]^T   grid (16, 4)
// =====================================================================
__global__ __launch_bounds__(256) void k_gemmC()
{
  extern __shared__ char smem[];
  const int t = threadIdx.x, lane = t & 31, wid = t >> 5;
  const int r0b = blockIdx.x*128;
  const int ch0 = blockIdx.y*128;

  Frag F;
  gemm_core3(smem_u32(smem), r0b, g_fgf, C2, ch0, g_w3_h, g_w3_l, CF, 0, C2/KC, F);

  const int wm = (wid & 1)*64, wn = (wid >> 1)*32;
  const int r0 = lane >> 2, cp = (lane & 3)*2;
  #pragma unroll
  for (int mi=0;mi<4;mi++){
    size_t ga = (size_t)(r0b + wm + mi*16 + r0), gb = ga + 8;
    #pragma unroll
    for (int ni=0;ni<4;ni++){
      int ch = ch0 + wn + ni*8 + cp;
      *(float2*)(g_G + ga*CF + ch) = make_float2(F.acc[mi][ni][0], F.acc[mi][ni][1]);
      *(float2*)(g_G + gb*CF + ch) = make_float2(F.acc[mi][ni][2], F.acc[mi][ni][3]);
    }
  }
}

// =====================================================================
// GEMM2 (fp16 2-term, K=256): h2 = relu(bn2(feat @ w3[:,256:]^T + G))
// -> single fp16 plane.  grid (2048, 4)
// =====================================================================
__global__ __launch_bounds__(256) void k_gemm2()
{
  extern __shared__ char smem[];
  __shared__ int scl[128];
  const int t = threadIdx.x, lane = t & 31, wid = t >> 5;
  const int p0 = blockIdx.x*128, bb = blockIdx.x >> 6;
  const int ch0 = blockIdx.y*128;

  for (int i=t; i<128; i+=256) scl[i] = g_chs[p0+i];
  __syncthreads();

  Frag F;
  gemm_core3(smem_u32(smem), p0, g_featf, C2, ch0, g_w3_h, g_w3_l, CF, C2, C2/KC, F);

  const int wm = (wid & 1)*64, wn = (wid >> 1)*32;
  const int r0 = lane >> 2, cp = (lane & 3)*2;
  #pragma unroll
  for (int mi=0;mi<4;mi++){
    int pa = wm + mi*16 + r0;
    size_t ga = (size_t)(p0 + pa), gb = ga + 8;
    const float* Ga = &g_G[(size_t)(bb*NCLST + scl[pa])*CF];
    const float* Gb = &g_G[(size_t)(bb*NCLST + scl[pa+8])*CF];
    #pragma unroll
    for (int ni=0;ni<4;ni++){
      int ch = ch0 + wn + ni*8 + cp;
      float s0 = g_s2[ch], s1 = g_s2[ch+1];
      float t0 = g_t2[ch], t1 = g_t2[ch+1];
      float2 gva = *(const float2*)(Ga + ch);
      float2 gvb = *(const float2*)(Gb + ch);
      float x0 = fmaxf(fmaf(F.acc[mi][ni][0] + gva.x, s0, t0), 0.f);
      float x1 = fmaxf(fmaf(F.acc[mi][ni][1] + gva.y, s1, t1), 0.f);
      float y0 = fmaxf(fmaf(F.acc[mi][ni][2] + gvb.x, s0, t0), 0.f);
      float y1 = fmaxf(fmaf(F.acc[mi][ni][3] + gvb.y, s1, t1), 0.f);
      uint32_t px = (uint32_t)__half_as_ushort(__float2half_rn(x0))
                  | ((uint32_t)__half_as_ushort(__float2half_rn(x1)) << 16);
      uint32_t py = (uint32_t)__half_as_ushort(__float2half_rn(y0))
                  | ((uint32_t)__half_as_ushort(__float2half_rn(y1)) << 16);
      *(uint32_t*)(g_h2f + ga*CF + ch) = px;
      *(uint32_t*)(g_h2f + gb*CF + ch) = py;
    }
  }
}

// =====================================================================
// GEMM3 (fp16 2-term, K=512): out = h2 @ w4^T + b4 -> segment max
// grid (2048, 3)
// =====================================================================
__global__ __launch_bounds__(256) void k_gemm3(const float* __restrict__ b4)
{
  extern __shared__ char smem[];
  __shared__ int scl[128];
  const int t = threadIdx.x, lane = t & 31, wid = t >> 5;
  const int p0 = blockIdx.x*128, bb = blockIdx.x >> 6;
  const int ch0 = blockIdx.y*128;

  for (int i=t; i<128; i+=256) scl[i] = g_chs[p0+i];
  __syncthreads();

  Frag F;
  gemm_core3(smem_u32(smem), p0, g_h2f, CF, ch0, g_w4_h, g_w4_l, CF, 0, CF/KC, F);

  float* Sv = (float*)smem;
  const int wm = (wid & 1)*64, wn = (wid >> 1)*32;
  const int r0 = lane >> 2, cp = (lane & 3)*2;
  #pragma unroll
  for (int mi=0;mi<4;mi++){
    int pa = wm + mi*16 + r0;
    #pragma unroll
    for (int ni=0;ni<4;ni++){
      int chl = wn + ni*8 + cp;
      int ch  = ch0 + chl;
      float b0 = b4[ch], b1 = b4[ch+1];
      *(float2*)&Sv[(size_t)pa*SVSTR + chl] =
          make_float2(F.acc[mi][ni][0] + b0, F.acc[mi][ni][1] + b1);
      *(float2*)&Sv[(size_t)(pa+8)*SVSTR + chl] =
          make_float2(F.acc[mi][ni][2] + b0, F.acc[mi][ni][3] + b1);
    }
  }
  __syncthreads();

  {
    const int ch = t & 127, half = t >> 7;
    int r = half*64;
    int cprev = scl[r];
    float run = __int_as_float(0xff800000);
    unsigned* omb = &g_om[(size_t)bb*NCLST*CO + ch0 + ch];
    for (int i=0;i<64;i++,r++){
      int c = scl[r];
      if (c != cprev){
        atomicMax(&omb[(size_t)cprev*CO], enc(run));
        run = __int_as_float(0xff800000);
        cprev = c;
      }
      run = fmaxf(run, Sv[(size_t)r*SVSTR + ch]);
    }
    atomicMax(&omb[(size_t)cprev*CO], enc(run));
  }
}

__global__ void k_final(float* __restrict__ out){
  int i = blockIdx.x*blockDim.x + threadIdx.x;
  if (i < NFG*CO) out[i] = dec(g_om[i]);
}

// =====================================================================
extern "C" void kernel_launch(void* const* d_in, const int* in_sizes, int n_in,
                              void* d_out, int out_size)
{
  const float* xyz    = (const float*)d_in[0];
  const int*   choice = (const int*)  d_in[1];
  const float* w1  = (const float*)d_in[2];
  const float* b1  = (const float*)d_in[3];
  const float* g1  = (const float*)d_in[4];
  const float* bb1 = (const float*)d_in[5];
  const float* m1  = (const float*)d_in[6];
  const float* v1  = (const float*)d_in[7];
  const float* w2  = (const float*)d_in[8];
  const float* b2  = (const float*)d_in[9];
  const float* w3  = (const float*)d_in[10];
  const float* b3  = (const float*)d_in[11];
  const float* g2  = (const float*)d_in[12];
  const float* bb2 = (const float*)d_in[13];
  const float* m2  = (const float*)d_in[14];
  const float* v2  = (const float*)d_in[15];
  const float* w4  = (const float*)d_in[16];
  const float* b4  = (const float*)d_in[17];

  size_t smem1 = SVB;        // 66560 (bf16 staging 40960 fits)
  size_t smem3 = 2*BUF3;     // 61440
  size_t smem3s = SVB;       // 66560 for gemm3 (needs Sv)
  cudaFuncSetAttribute(k_stage1, cudaFuncAttributeMaxDynamicSharedMemorySize, (int)smem1);
  cudaFuncSetAttribute(k_gemmC,  cudaFuncAttributeMaxDynamicSharedMemorySize, (int)smem3);
  cudaFuncSetAttribute(k_gemm2,  cudaFuncAttributeMaxDynamicSharedMemorySize, (int)smem3);
  cudaFuncSetAttribute(k_gemm3,  cudaFuncAttributeMaxDynamicSharedMemorySize, (int)smem3s);

  int nprep = NFG*CO;

  k_sort    <<<BATCH, 256>>>(choice);
  k_prep    <<<(nprep+255)/256, 256>>>(w1,b1,g1,bb1,m1,v1,w2, w3,w4,b3,g2,bb2,m2,v2);
  {
    dim3 g1d(PTOT/128, C2/128);   // (2048, 2)
    k_stage1<<<g1d, 256, smem1>>>(xyz, b2);
  }
  k_fg_split<<<(NFG*C2+255)/256, 256>>>();
  {
    dim3 gcd(NFG/128, CF/128);    // (16, 4)
    k_gemmC<<<gcd, 256, smem3>>>();
    dim3 g2d(PTOT/128, CF/128);   // (2048, 4)
    k_gemm2<<<g2d, 256, smem3>>>();
    dim3 g3d(PTOT/128, CO/128);   // (2048, 3)
    k_gemm3<<<g3d, 256, smem3s>>>(b4);
  }
  k_final   <<<(NFG*CO+255)/256, 256>>>((float*)d_out);
}

// round 15
// speedup vs baseline: 1.4387x; 1.0328x over previous
#include <cuda_runtime.h>
#include <cuda_bf16.h>
#include <cuda_fp16.h>
#include <stdint.h>

#define BATCH 32
#define NPTS  8192
#define NCLST 64
#define C1    128
#define C2    256
#define CF    512
#define CO    384
#define PTOT  (BATCH*NPTS)
#define NFG   (BATCH*NCLST)
#define ENC_NEG_INF 0x007FFFFFu

#define ROWB   80
#define PLANE  (128*ROWB)       // 10240 B
#define BUF3   (3*PLANE)        // 30720 B (fp16 core: A,Bh,Bl)
#define KC     32
#define SVSTR  130
#define SVB    (128*SVSTR*4)    // 66560 B

// ---------------- scratch ----------------
__device__ unsigned g_fg[NFG*C2];
__device__ unsigned g_om[NFG*CO];
__device__ int g_perm[PTOT];
__device__ int g_chs[PTOT];
__device__ __align__(16) uint16_t g_featf[(size_t)PTOT*C2];  // feat fp16
__device__ __align__(16) uint16_t g_fgf[NFG*C2];             // fg fp16
__device__ __align__(16) uint16_t g_h2f[(size_t)PTOT*CF];    // h2 fp16
__device__ __align__(16) uint16_t g_w2_h[C2*C1], g_w2_l[C2*C1];   // fp16 split
__device__ __align__(16) uint16_t g_w3_h[CF*CF], g_w3_l[CF*CF];   // fp16 split
__device__ __align__(16) uint16_t g_w4_h[CO*CF], g_w4_l[CO*CF];   // fp16 split
__device__ float g_G[(size_t)NFG*CF];
__device__ float g_s2[CF], g_t2[CF];
__device__ __align__(16) float g_w1f[C1*4];

// ---------------- helpers ----------------
__device__ __forceinline__ unsigned enc(float f){
  unsigned u = __float_as_uint(f);
  return (u & 0x80000000u) ? ~u : (u | 0x80000000u);
}
__device__ __forceinline__ float dec(unsigned u){
  u = (u & 0x80000000u) ? (u & 0x7FFFFFFFu) : ~u;
  return __uint_as_float(u);
}
__device__ __forceinline__ void split2h(float v, uint16_t& h, uint16_t& l){
  __half hh = __float2half_rn(v);
  float r = v - __half2float(hh);
  if (!(r == r)) r = 0.f;
  h = __half_as_ushort(hh);
  l = __half_as_ushort(__float2half_rn(r));
}
__device__ __forceinline__ uint32_t smem_u32(const void* p){
  uint32_t a;
  asm("{ .reg .u64 t; cvta.to.shared.u64 t, %1; cvt.u32.u64 %0, t; }" : "=r"(a) : "l"(p));
  return a;
}
__device__ __forceinline__ void cp16(uint32_t dst, const void* src){
  asm volatile("cp.async.cg.shared.global [%0], [%1], 16;" :: "r"(dst), "l"(src));
}
#define CP_COMMIT() asm volatile("cp.async.commit_group;" ::: "memory")
#define CP_WAIT1()  asm volatile("cp.async.wait_group 1;"  ::: "memory")
#define CP_WAIT0()  asm volatile("cp.async.wait_group 0;"  ::: "memory")

__device__ __forceinline__ void ldsm4(uint32_t* r, uint32_t addr){
  asm volatile("ldmatrix.sync.aligned.m8n8.x4.shared.b16 {%0,%1,%2,%3}, [%4];"
    : "=r"(r[0]),"=r"(r[1]),"=r"(r[2]),"=r"(r[3]) : "r"(addr));
}
__device__ __forceinline__ void mma16816h(float* c, const uint32_t* a, const uint32_t* b){
  asm volatile("mma.sync.aligned.m16n8k16.row.col.f32.f16.f16.f32 "
    "{%0,%1,%2,%3}, {%4,%5,%6,%7}, {%8,%9}, {%0,%1,%2,%3};"
    : "+f"(c[0]),"+f"(c[1]),"+f"(c[2]),"+f"(c[3])
    : "r"(a[0]),"r"(a[1]),"r"(a[2]),"r"(a[3]), "r"(b[0]),"r"(b[1]));
}

struct Frag { float acc[4][4][4]; };

// fp16 2-term chunk: A single plane, B split hi/lo
__device__ __forceinline__ void mma_chunk3(uint32_t sb, uint32_t aoff, uint32_t boff, Frag& F){
  const uint32_t aA = sb, aBh = sb + PLANE, aBl = sb + 2*PLANE;
  #pragma unroll
  for (int ks = 0; ks < 2; ks++){
    const uint32_t kb = ks * 32;
    uint32_t a[4][4], bH[2][4], bL[2][4];
    #pragma unroll
    for (int mi=0;mi<4;mi++) ldsm4(a[mi],  aA  + aoff + mi*(16*ROWB) + kb);
    #pragma unroll
    for (int nj=0;nj<2;nj++) ldsm4(bH[nj], aBh + boff + nj*(16*ROWB) + kb);
    #pragma unroll
    for (int mi=0;mi<4;mi++)
      #pragma unroll
      for (int nj=0;nj<2;nj++){
        mma16816h(F.acc[mi][nj*2+0], a[mi], &bH[nj][0]);
        mma16816h(F.acc[mi][nj*2+1], a[mi], &bH[nj][2]);
      }
    #pragma unroll
    for (int nj=0;nj<2;nj++) ldsm4(bL[nj], aBl + boff + nj*(16*ROWB) + kb);
    #pragma unroll
    for (int mi=0;mi<4;mi++)
      #pragma unroll
      for (int nj=0;nj<2;nj++){
        mma16816h(F.acc[mi][nj*2+0], a[mi], &bL[nj][0]);
        mma16816h(F.acc[mi][nj*2+1], a[mi], &bL[nj][2]);
      }
  }
}

// fp16 2-term double-buffered core (A single plane, B split)
__device__ __forceinline__ void gemm_core3(
    uint32_t sb0, int arow0, const uint16_t* __restrict__ Af, int astride,
    int ch0, const uint16_t* __restrict__ Bh, const uint16_t* __restrict__ Bl,
    int bstride, int bkoff, int NKC, Frag& F)
{
  const int t = threadIdx.x, lane = t & 31, wid = t >> 5;
  const int wm = (wid & 1)*64, wn = (wid >> 1)*32;
  const uint32_t aoff = (uint32_t)(wm + (lane & 15))*ROWB + ((lane >> 4) & 1)*16;
  const uint32_t boff = (uint32_t)(wn + (lane & 7) + ((lane >> 4) & 1)*8)*ROWB
                      + ((lane >> 3) & 1)*16;

  #pragma unroll
  for (int mi=0;mi<4;mi++)
    #pragma unroll
    for (int ni=0;ni<4;ni++)
      #pragma unroll
      for (int c=0;c<4;c++) F.acc[mi][ni][c] = 0.f;

  #define ISSUE3(kc) do { \
    uint32_t sbb = sb0 + ((kc)&1)*BUF3; \
    for (int idx=t; idx<512; idx+=256){ \
      int row = idx >> 2, c = idx & 3; \
      size_t offa = (size_t)(arow0 + row)*astride + (kc)*KC + c*8; \
      size_t offb = (size_t)(ch0 + row)*bstride + bkoff + (kc)*KC + c*8; \
      uint32_t so = (uint32_t)row*ROWB + c*16; \
      cp16(sbb + so,           Af + offa); \
      cp16(sbb + PLANE + so,   Bh + offb); \
      cp16(sbb + 2*PLANE + so, Bl + offb); \
    } \
    CP_COMMIT(); \
  } while(0)

  ISSUE3(0);
  for (int kc = 0; kc < NKC; kc++){
    if (kc + 1 < NKC){ ISSUE3(kc+1); CP_WAIT1(); }
    else             { CP_WAIT0(); }
    __syncthreads();
    mma_chunk3(sb0 + (kc&1)*BUF3, aoff, boff, F);
    __syncthreads();
  }
  #undef ISSUE3
}

// =====================================================================
__global__ __launch_bounds__(256) void k_sort(const int* __restrict__ choice){
  __shared__ int offs[NCLST];
  __shared__ int hist[NCLST];
  const int t = threadIdx.x, b = blockIdx.x;
  const int base = b*NPTS;
  if (t < NCLST){ hist[t] = 0; }
  __syncthreads();
  for (int i=t; i<NPTS; i+=256) atomicAdd(&hist[choice[base+i]], 1);
  __syncthreads();
  if (t == 0){
    int s = 0;
    for (int c=0;c<NCLST;c++){ offs[c] = s; s += hist[c]; }
  }
  __syncthreads();
  for (int i=t; i<NPTS; i+=256){
    int c = choice[base+i];
    int pos = atomicAdd(&offs[c], 1);
    g_perm[base+pos] = base + i;
    g_chs [base+pos] = c;
  }
}

__global__ void k_prep(
    const float* __restrict__ w1, const float* __restrict__ b1,
    const float* __restrict__ bg1, const float* __restrict__ bb1,
    const float* __restrict__ bm1, const float* __restrict__ bv1,
    const float* __restrict__ w2,
    const float* __restrict__ w3, const float* __restrict__ w4,
    const float* __restrict__ b3,
    const float* __restrict__ bg2, const float* __restrict__ bb2,
    const float* __restrict__ bm2, const float* __restrict__ bv2)
{
  int i = blockIdx.x*blockDim.x + threadIdx.x;
  if (i < NFG*C2) g_fg[i] = ENC_NEG_INF;
  if (i < NFG*CO) g_om[i] = ENC_NEG_INF;
  if (i < CF*CF){ uint16_t h,l; split2h(w3[i],h,l); g_w3_h[i]=h; g_w3_l[i]=l; }
  int j = i - CF*CF;
  if (j >= 0 && j < CO*CF){ uint16_t h,l; split2h(w4[j],h,l); g_w4_h[j]=h; g_w4_l[j]=l; }
  int k = i - CF*CF - CO*CF;
  if (k >= 0 && k < C2*C1){ uint16_t h,l; split2h(w2[k],h,l); g_w2_h[k]=h; g_w2_l[k]=l; }
  int m = i - CF*CF - CO*CF - C2*C1;
  if (m >= 0 && m < CF){
    float s = bg2[m] * rsqrtf(bv2[m] + 1e-5f);
    g_s2[m] = s;
    g_t2[m] = bb2[m] + (b3[m] - bm2[m]) * s;
  }
  int q = i - CF*CF - CO*CF - C2*C1 - CF;
  if (q >= 0 && q < C1){
    float s = bg1[q] * rsqrtf(bv1[q] + 1e-5f);
    g_w1f[q*4+0] = w1[q*3+0]*s;
    g_w1f[q*4+1] = w1[q*3+1]*s;
    g_w1f[q*4+2] = w1[q*3+2]*s;
    g_w1f[q*4+3] = (b1[q] - bm1[q])*s + bb1[q];
  }
}

// =====================================================================
// Stage 1 (fp16 2-term, inline h): feat fp16 + segment fg max. grid (2048,2)
// =====================================================================
__global__ __launch_bounds__(256) void k_stage1(
    const float* __restrict__ xyz, const float* __restrict__ b2)
{
  extern __shared__ char smem[];
  __shared__ float sx[128][3];
  __shared__ int   scl[128];
  __shared__ int   sperm[128];
  __shared__ __align__(16) float sw1[C1*4];

  const int t = threadIdx.x, lane = t & 31, wid = t >> 5;
  const int p0 = blockIdx.x*128, bb = blockIdx.x >> 6;
  const int ch0 = blockIdx.y*128;

  for (int i=t; i<128; i+=256){ scl[i] = g_chs[p0+i]; sperm[i] = g_perm[p0+i]; }
  for (int i=t; i<C1*4; i+=256) sw1[i] = g_w1f[i];
  __syncthreads();
  for (int i=t; i<128*3; i+=256) sx[i/3][i%3] = xyz[(size_t)sperm[i/3]*3 + (i%3)];
  __syncthreads();

  const uint32_t sb = smem_u32(smem);
  uint16_t* pA = (uint16_t*)smem;   // h fp16 plane

  const int wm = (wid & 1)*64, wn = (wid >> 1)*32;
  const uint32_t aoff = (uint32_t)(wm + (lane & 15))*ROWB + ((lane >> 4) & 1)*16;
  const uint32_t boff = (uint32_t)(wn + (lane & 7) + ((lane >> 4) & 1)*8)*ROWB
                      + ((lane >> 3) & 1)*16;

  Frag F;
  #pragma unroll
  for (int mi=0;mi<4;mi++)
    #pragma unroll
    for (int ni=0;ni<4;ni++)
      #pragma unroll
      for (int c=0;c<4;c++) F.acc[mi][ni][c] = 0.f;

  for (int kc=0; kc<4; kc++){
    for (int idx=t; idx<512; idx+=256){
      int row = idx >> 2, c = idx & 3;
      size_t off = (size_t)(ch0+row)*C1 + kc*KC + c*8;
      uint32_t so = (uint32_t)row*ROWB + c*16;
      cp16(sb + PLANE + so,   g_w2_h + off);
      cp16(sb + 2*PLANE + so, g_w2_l + off);
    }
    CP_COMMIT();
    for (int idx=t; idx<4096; idx+=256){
      int row = idx >> 5, kp = idx & 31;
      int k = kc*KC + kp;
      float4 wf = *(const float4*)(sw1 + 4*k);
      float h = fmaf(sx[row][0], wf.x, fmaf(sx[row][1], wf.y, fmaf(sx[row][2], wf.z, wf.w)));
      h = fmaxf(h, 0.f);
      pA[(uint32_t)row*(ROWB/2) + kp] = __half_as_ushort(__float2half_rn(h));
    }
    CP_WAIT0();
    __syncthreads();
    mma_chunk3(sb, aoff, boff, F);
    __syncthreads();
  }

  float* Sv = (float*)smem;
  const int r0 = lane >> 2, cp = (lane & 3)*2;
  #pragma unroll
  for (int mi=0;mi<4;mi++){
    int pa = wm + mi*16 + r0;
    size_t ga = (size_t)(p0 + pa), gb = ga + 8;
    #pragma unroll
    for (int ni=0;ni<4;ni++){
      int chl = wn + ni*8 + cp;
      int ch  = ch0 + chl;
      float b0 = b2[ch], b1v = b2[ch+1];
      // fp16 rounding applied BEFORE the fg max so fg == max over stored feat
      float x0 = __half2float(__float2half_rn(F.acc[mi][ni][0] + b0));
      float x1 = __half2float(__float2half_rn(F.acc[mi][ni][1] + b1v));
      float y0 = __half2float(__float2half_rn(F.acc[mi][ni][2] + b0));
      float y1 = __half2float(__float2half_rn(F.acc[mi][ni][3] + b1v));
      uint32_t px = (uint32_t)__half_as_ushort(__float2half_rn(x0))
                  | ((uint32_t)__half_as_ushort(__float2half_rn(x1)) << 16);
      uint32_t py = (uint32_t)__half_as_ushort(__float2half_rn(y0))
                  | ((uint32_t)__half_as_ushort(__float2half_rn(y1)) << 16);
      *(uint32_t*)(g_featf + ga*C2 + ch) = px;
      *(uint32_t*)(g_featf + gb*C2 + ch) = py;
      *(float2*)&Sv[(size_t)pa*SVSTR + chl]     = make_float2(x0, x1);
      *(float2*)&Sv[(size_t)(pa+8)*SVSTR + chl] = make_float2(y0, y1);
    }
  }
  __syncthreads();

  {
    const int ch = t & 127, half = t >> 7;
    int r = half*64;
    int cprev = scl[r];
    float run = __int_as_float(0xff800000);
    unsigned* fgb = &g_fg[(size_t)bb*NCLST*C2 + ch0 + ch];
    for (int i=0;i<64;i++,r++){
      int c = scl[r];
      if (c != cprev){
        atomicMax(&fgb[(size_t)cprev*C2], enc(run));
        run = __int_as_float(0xff800000);
        cprev = c;
      }
      run = fmaxf(run, Sv[(size_t)r*SVSTR + ch]);
    }
    atomicMax(&fgb[(size_t)cprev*C2], enc(run));
  }
}

__global__ void k_fg_split(){
  int i = blockIdx.x*blockDim.x + threadIdx.x;
  if (i < NFG*C2)
    g_fgf[i] = __half_as_ushort(__float2half_rn(dec(g_fg[i])));
}

// =====================================================================
// Cluster GEMM (fp16 2-term): G = fg @ w3[:, :256]^T   grid (16, 4)
// =====================================================================
__global__ __launch_bounds__(256) void k_gemmC()
{
  extern __shared__ char smem[];
  const int t = threadIdx.x, lane = t & 31, wid = t >> 5;
  const int r0b = blockIdx.x*128;
  const int ch0 = blockIdx.y*128;

  Frag F;
  gemm_core3(smem_u32(smem), r0b, g_fgf, C2, ch0, g_w3_h, g_w3_l, CF, 0, C2/KC, F);

  const int wm = (wid & 1)*64, wn = (wid >> 1)*32;
  const int r0 = lane >> 2, cp = (lane & 3)*2;
  #pragma unroll
  for (int mi=0;mi<4;mi++){
    size_t ga = (size_t)(r0b + wm + mi*16 + r0), gb = ga + 8;
    #pragma unroll
    for (int ni=0;ni<4;ni++){
      int ch = ch0 + wn + ni*8 + cp;
      *(float2*)(g_G + ga*CF + ch) = make_float2(F.acc[mi][ni][0], F.acc[mi][ni][1]);
      *(float2*)(g_G + gb*CF + ch) = make_float2(F.acc[mi][ni][2], F.acc[mi][ni][3]);
    }
  }
}

// =====================================================================
// GEMM2 (fp16 2-term, K=256): h2 = relu(bn2(feat @ w3[:,256:]^T + G))
// grid (2048, 4)
// =====================================================================
__global__ __launch_bounds__(256) void k_gemm2()
{
  extern __shared__ char smem[];
  __shared__ int scl[128];
  const int t = threadIdx.x, lane = t & 31, wid = t >> 5;
  const int p0 = blockIdx.x*128, bb = blockIdx.x >> 6;
  const int ch0 = blockIdx.y*128;

  for (int i=t; i<128; i+=256) scl[i] = g_chs[p0+i];
  __syncthreads();

  Frag F;
  gemm_core3(smem_u32(smem), p0, g_featf, C2, ch0, g_w3_h, g_w3_l, CF, C2, C2/KC, F);

  const int wm = (wid & 1)*64, wn = (wid >> 1)*32;
  const int r0 = lane >> 2, cp = (lane & 3)*2;
  #pragma unroll
  for (int mi=0;mi<4;mi++){
    int pa = wm + mi*16 + r0;
    size_t ga = (size_t)(p0 + pa), gb = ga + 8;
    const float* Ga = &g_G[(size_t)(bb*NCLST + scl[pa])*CF];
    const float* Gb = &g_G[(size_t)(bb*NCLST + scl[pa+8])*CF];
    #pragma unroll
    for (int ni=0;ni<4;ni++){
      int ch = ch0 + wn + ni*8 + cp;
      float s0 = g_s2[ch], s1 = g_s2[ch+1];
      float t0 = g_t2[ch], t1 = g_t2[ch+1];
      float2 gva = *(const float2*)(Ga + ch);
      float2 gvb = *(const float2*)(Gb + ch);
      float x0 = fmaxf(fmaf(F.acc[mi][ni][0] + gva.x, s0, t0), 0.f);
      float x1 = fmaxf(fmaf(F.acc[mi][ni][1] + gva.y, s1, t1), 0.f);
      float y0 = fmaxf(fmaf(F.acc[mi][ni][2] + gvb.x, s0, t0), 0.f);
      float y1 = fmaxf(fmaf(F.acc[mi][ni][3] + gvb.y, s1, t1), 0.f);
      uint32_t px = (uint32_t)__half_as_ushort(__float2half_rn(x0))
                  | ((uint32_t)__half_as_ushort(__float2half_rn(x1)) << 16);
      uint32_t py = (uint32_t)__half_as_ushort(__float2half_rn(y0))
                  | ((uint32_t)__half_as_ushort(__float2half_rn(y1)) << 16);
      *(uint32_t*)(g_h2f + ga*CF + ch) = px;
      *(uint32_t*)(g_h2f + gb*CF + ch) = py;
    }
  }
}

// =====================================================================
// GEMM3 (fp16 2-term, K=512): out = h2 @ w4^T + b4 -> segment max
// grid (2048, 3)
// =====================================================================
__global__ __launch_bounds__(256) void k_gemm3(const float* __restrict__ b4)
{
  extern __shared__ char smem[];
  __shared__ int scl[128];
  const int t = threadIdx.x, lane = t & 31, wid = t >> 5;
  const int p0 = blockIdx.x*128, bb = blockIdx.x >> 6;
  const int ch0 = blockIdx.y*128;

  for (int i=t; i<128; i+=256) scl[i] = g_chs[p0+i];
  __syncthreads();

  Frag F;
  gemm_core3(smem_u32(smem), p0, g_h2f, CF, ch0, g_w4_h, g_w4_l, CF, 0, CF/KC, F);

  float* Sv = (float*)smem;
  const int wm = (wid & 1)*64, wn = (wid >> 1)*32;
  const int r0 = lane >> 2, cp = (lane & 3)*2;
  #pragma unroll
  for (int mi=0;mi<4;mi++){
    int pa = wm + mi*16 + r0;
    #pragma unroll
    for (int ni=0;ni<4;ni++){
      int chl = wn + ni*8 + cp;
      int ch  = ch0 + chl;
      float b0 = b4[ch], b1 = b4[ch+1];
      *(float2*)&Sv[(size_t)pa*SVSTR + chl] =
          make_float2(F.acc[mi][ni][0] + b0, F.acc[mi][ni][1] + b1);
      *(float2*)&Sv[(size_t)(pa+8)*SVSTR + chl] =
          make_float2(F.acc[mi][ni][2] + b0, F.acc[mi][ni][3] + b1);
    }
  }
  __syncthreads();

  {
    const int ch = t & 127, half = t >> 7;
    int r = half*64;
    int cprev = scl[r];
    float run = __int_as_float(0xff800000);
    unsigned* omb = &g_om[(size_t)bb*NCLST*CO + ch0 + ch];
    for (int i=0;i<64;i++,r++){
      int c = scl[r];
      if (c != cprev){
        atomicMax(&omb[(size_t)cprev*CO], enc(run));
        run = __int_as_float(0xff800000);
        cprev = c;
      }
      run = fmaxf(run, Sv[(size_t)r*SVSTR + ch]);
    }
    atomicMax(&omb[(size_t)cprev*CO], enc(run));
  }
}

__global__ void k_final(float* __restrict__ out){
  int i = blockIdx.x*blockDim.x + threadIdx.x;
  if (i < NFG*CO) out[i] = dec(g_om[i]);
}

// =====================================================================
extern "C" void kernel_launch(void* const* d_in, const int* in_sizes, int n_in,
                              void* d_out, int out_size)
{
  const float* xyz    = (const float*)d_in[0];
  const int*   choice = (const int*)  d_in[1];
  const float* w1  = (const float*)d_in[2];
  const float* b1  = (const float*)d_in[3];
  const float* g1  = (const float*)d_in[4];
  const float* bb1 = (const float*)d_in[5];
  const float* m1  = (const float*)d_in[6];
  const float* v1  = (const float*)d_in[7];
  const float* w2  = (const float*)d_in[8];
  const float* b2  = (const float*)d_in[9];
  const float* w3  = (const float*)d_in[10];
  const float* b3  = (const float*)d_in[11];
  const float* g2  = (const float*)d_in[12];
  const float* bb2 = (const float*)d_in[13];
  const float* m2  = (const float*)d_in[14];
  const float* v2  = (const float*)d_in[15];
  const float* w4  = (const float*)d_in[16];
  const float* b4  = (const float*)d_in[17];

  size_t smem1  = SVB;       // 66560 (fp16 staging 30720 fits; Sv needs 66560)
  size_t smem3  = 2*BUF3;    // 61440
  size_t smem3s = SVB;       // 66560 for gemm3 (needs Sv)
  cudaFuncSetAttribute(k_stage1, cudaFuncAttributeMaxDynamicSharedMemorySize, (int)smem1);
  cudaFuncSetAttribute(k_gemmC,  cudaFuncAttributeMaxDynamicSharedMemorySize, (int)smem3);
  cudaFuncSetAttribute(k_gemm2,  cudaFuncAttributeMaxDynamicSharedMemorySize, (int)smem3);
  cudaFuncSetAttribute(k_gemm3,  cudaFuncAttributeMaxDynamicSharedMemorySize, (int)smem3s);

  int nprep = NFG*CO;

  k_sort    <<<BATCH, 256>>>(choice);
  k_prep    <<<(nprep+255)/256, 256>>>(w1,b1,g1,bb1,m1,v1,w2, w3,w4,b3,g2,bb2,m2,v2);
  {
    dim3 g1d(PTOT/128, C2/128);   // (2048, 2)
    k_stage1<<<g1d, 256, smem1>>>(xyz, b2);
  }
  k_fg_split<<<(NFG*C2+255)/256, 256>>>();
  {
    dim3 gcd(NFG/128, CF/128);    // (16, 4)
    k_gemmC<<<gcd, 256, smem3>>>();
    dim3 g2d(PTOT/128, CF/128);   // (2048, 4)
    k_gemm2<<<g2d, 256, smem3>>>();
    dim3 g3d(PTOT/128, CO/128);   // (2048, 3)
    k_gemm3<<<g3d, 256, smem3s>>>(b4);
  }
  k_final   <<<(NFG*CO+255)/256, 256>>>((float*)d_out);
}

// round 16
// speedup vs baseline: 2.0106x; 1.3975x over previous
#include <cuda_runtime.h>
#include <cuda_bf16.h>
#include <cuda_fp16.h>
#include <stdint.h>

#define BATCH 32
#define NPTS  8192
#define NCLST 64
#define C1    128
#define C2    256
#define CF    512
#define CO    384
#define PTOT  (BATCH*NPTS)
#define NFG   (BATCH*NCLST)
#define ENC_NEG_INF 0x007FFFFFu

#define ROWB   80
#define PLANE  (128*ROWB)       // 10240 B
#define BUF3   (3*PLANE)        // 30720 B (2-term core: A,Bh,Bl)
#define BUF1   (2*PLANE)        // 20480 B (1-term core: A,B)
#define KC     32
#define SVSTR  130
#define SVB    (128*SVSTR*4)    // 66560 B

// ---------------- scratch ----------------
__device__ unsigned g_fg[NFG*C2];
__device__ unsigned g_om[NFG*CO];
__device__ int g_perm[PTOT];
__device__ int g_chs[PTOT];
__device__ __align__(16) uint16_t g_featf[(size_t)PTOT*C2];  // feat fp16
__device__ __align__(16) uint16_t g_fgf[NFG*C2];             // fg fp16
__device__ __align__(16) uint16_t g_h2f[(size_t)PTOT*CF];    // h2 fp16
__device__ __align__(16) uint16_t g_w2_h[C2*C1], g_w2_l[C2*C1];   // fp16 split
__device__ __align__(16) uint16_t g_w3_h[CF*CF], g_w3_l[CF*CF];   // fp16 split (lo used by gemmC only)
__device__ __align__(16) uint16_t g_w4_h[CO*CF];                  // fp16 single
__device__ float g_G[(size_t)NFG*CF];
__device__ float g_s2[CF], g_t2[CF];
__device__ __align__(16) float g_w1f[C1*4];

// ---------------- helpers ----------------
__device__ __forceinline__ unsigned enc(float f){
  unsigned u = __float_as_uint(f);
  return (u & 0x80000000u) ? ~u : (u | 0x80000000u);
}
__device__ __forceinline__ float dec(unsigned u){
  u = (u & 0x80000000u) ? (u & 0x7FFFFFFFu) : ~u;
  return __uint_as_float(u);
}
__device__ __forceinline__ void split2h(float v, uint16_t& h, uint16_t& l){
  __half hh = __float2half_rn(v);
  float r = v - __half2float(hh);
  if (!(r == r)) r = 0.f;
  h = __half_as_ushort(hh);
  l = __half_as_ushort(__float2half_rn(r));
}
__device__ __forceinline__ uint32_t smem_u32(const void* p){
  uint32_t a;
  asm("{ .reg .u64 t; cvta.to.shared.u64 t, %1; cvt.u32.u64 %0, t; }" : "=r"(a) : "l"(p));
  return a;
}
__device__ __forceinline__ void cp16(uint32_t dst, const void* src){
  asm volatile("cp.async.cg.shared.global [%0], [%1], 16;" :: "r"(dst), "l"(src));
}
#define CP_COMMIT() asm volatile("cp.async.commit_group;" ::: "memory")
#define CP_WAIT1()  asm volatile("cp.async.wait_group 1;"  ::: "memory")
#define CP_WAIT0()  asm volatile("cp.async.wait_group 0;"  ::: "memory")

__device__ __forceinline__ void ldsm4(uint32_t* r, uint32_t addr){
  asm volatile("ldmatrix.sync.aligned.m8n8.x4.shared.b16 {%0,%1,%2,%3}, [%4];"
    : "=r"(r[0]),"=r"(r[1]),"=r"(r[2]),"=r"(r[3]) : "r"(addr));
}
__device__ __forceinline__ void mma16816h(float* c, const uint32_t* a, const uint32_t* b){
  asm volatile("mma.sync.aligned.m16n8k16.row.col.f32.f16.f16.f32 "
    "{%0,%1,%2,%3}, {%4,%5,%6,%7}, {%8,%9}, {%0,%1,%2,%3};"
    : "+f"(c[0]),"+f"(c[1]),"+f"(c[2]),"+f"(c[3])
    : "r"(a[0]),"r"(a[1]),"r"(a[2]),"r"(a[3]), "r"(b[0]),"r"(b[1]));
}

struct Frag { float acc[4][4][4]; };

// fp16 2-term chunk: A single plane, B split hi/lo
__device__ __forceinline__ void mma_chunk3(uint32_t sb, uint32_t aoff, uint32_t boff, Frag& F){
  const uint32_t aA = sb, aBh = sb + PLANE, aBl = sb + 2*PLANE;
  #pragma unroll
  for (int ks = 0; ks < 2; ks++){
    const uint32_t kb = ks * 32;
    uint32_t a[4][4], bH[2][4], bL[2][4];
    #pragma unroll
    for (int mi=0;mi<4;mi++) ldsm4(a[mi],  aA  + aoff + mi*(16*ROWB) + kb);
    #pragma unroll
    for (int nj=0;nj<2;nj++) ldsm4(bH[nj], aBh + boff + nj*(16*ROWB) + kb);
    #pragma unroll
    for (int mi=0;mi<4;mi++)
      #pragma unroll
      for (int nj=0;nj<2;nj++){
        mma16816h(F.acc[mi][nj*2+0], a[mi], &bH[nj][0]);
        mma16816h(F.acc[mi][nj*2+1], a[mi], &bH[nj][2]);
      }
    #pragma unroll
    for (int nj=0;nj<2;nj++) ldsm4(bL[nj], aBl + boff + nj*(16*ROWB) + kb);
    #pragma unroll
    for (int mi=0;mi<4;mi++)
      #pragma unroll
      for (int nj=0;nj<2;nj++){
        mma16816h(F.acc[mi][nj*2+0], a[mi], &bL[nj][0]);
        mma16816h(F.acc[mi][nj*2+1], a[mi], &bL[nj][2]);
      }
  }
}

// fp16 1-term chunk: A plane, B plane
__device__ __forceinline__ void mma_chunk1(uint32_t sb, uint32_t aoff, uint32_t boff, Frag& F){
  const uint32_t aA = sb, aB = sb + PLANE;
  #pragma unroll
  for (int ks = 0; ks < 2; ks++){
    const uint32_t kb = ks * 32;
    uint32_t a[4][4], b[2][4];
    #pragma unroll
    for (int mi=0;mi<4;mi++) ldsm4(a[mi], aA + aoff + mi*(16*ROWB) + kb);
    #pragma unroll
    for (int nj=0;nj<2;nj++) ldsm4(b[nj], aB + boff + nj*(16*ROWB) + kb);
    #pragma unroll
    for (int mi=0;mi<4;mi++)
      #pragma unroll
      for (int nj=0;nj<2;nj++){
        mma16816h(F.acc[mi][nj*2+0], a[mi], &b[nj][0]);
        mma16816h(F.acc[mi][nj*2+1], a[mi], &b[nj][2]);
      }
  }
}

// fp16 2-term double-buffered core
__device__ __forceinline__ void gemm_core3(
    uint32_t sb0, int arow0, const uint16_t* __restrict__ Af, int astride,
    int ch0, const uint16_t* __restrict__ Bh, const uint16_t* __restrict__ Bl,
    int bstride, int bkoff, int NKC, Frag& F)
{
  const int t = threadIdx.x, lane = t & 31, wid = t >> 5;
  const int wm = (wid & 1)*64, wn = (wid >> 1)*32;
  const uint32_t aoff = (uint32_t)(wm + (lane & 15))*ROWB + ((lane >> 4) & 1)*16;
  const uint32_t boff = (uint32_t)(wn + (lane & 7) + ((lane >> 4) & 1)*8)*ROWB
                      + ((lane >> 3) & 1)*16;

  #pragma unroll
  for (int mi=0;mi<4;mi++)
    #pragma unroll
    for (int ni=0;ni<4;ni++)
      #pragma unroll
      for (int c=0;c<4;c++) F.acc[mi][ni][c] = 0.f;

  #define ISSUE3(kc) do { \
    uint32_t sbb = sb0 + ((kc)&1)*BUF3; \
    for (int idx=t; idx<512; idx+=256){ \
      int row = idx >> 2, c = idx & 3; \
      size_t offa = (size_t)(arow0 + row)*astride + (kc)*KC + c*8; \
      size_t offb = (size_t)(ch0 + row)*bstride + bkoff + (kc)*KC + c*8; \
      uint32_t so = (uint32_t)row*ROWB + c*16; \
      cp16(sbb + so,           Af + offa); \
      cp16(sbb + PLANE + so,   Bh + offb); \
      cp16(sbb + 2*PLANE + so, Bl + offb); \
    } \
    CP_COMMIT(); \
  } while(0)

  ISSUE3(0);
  for (int kc = 0; kc < NKC; kc++){
    if (kc + 1 < NKC){ ISSUE3(kc+1); CP_WAIT1(); }
    else             { CP_WAIT0(); }
    __syncthreads();
    mma_chunk3(sb0 + (kc&1)*BUF3, aoff, boff, F);
    __syncthreads();
  }
  #undef ISSUE3
}

// fp16 1-term double-buffered core
__device__ __forceinline__ void gemm_core1(
    uint32_t sb0, int arow0, const uint16_t* __restrict__ Af, int astride,
    int ch0, const uint16_t* __restrict__ B, int bstride, int bkoff,
    int NKC, Frag& F)
{
  const int t = threadIdx.x, lane = t & 31, wid = t >> 5;
  const int wm = (wid & 1)*64, wn = (wid >> 1)*32;
  const uint32_t aoff = (uint32_t)(wm + (lane & 15))*ROWB + ((lane >> 4) & 1)*16;
  const uint32_t boff = (uint32_t)(wn + (lane & 7) + ((lane >> 4) & 1)*8)*ROWB
                      + ((lane >> 3) & 1)*16;

  #pragma unroll
  for (int mi=0;mi<4;mi++)
    #pragma unroll
    for (int ni=0;ni<4;ni++)
      #pragma unroll
      for (int c=0;c<4;c++) F.acc[mi][ni][c] = 0.f;

  #define ISSUE1(kc) do { \
    uint32_t sbb = sb0 + ((kc)&1)*BUF1; \
    for (int idx=t; idx<512; idx+=256){ \
      int row = idx >> 2, c = idx & 3; \
      size_t offa = (size_t)(arow0 + row)*astride + (kc)*KC + c*8; \
      size_t offb = (size_t)(ch0 + row)*bstride + bkoff + (kc)*KC + c*8; \
      uint32_t so = (uint32_t)row*ROWB + c*16; \
      cp16(sbb + so,         Af + offa); \
      cp16(sbb + PLANE + so, B + offb); \
    } \
    CP_COMMIT(); \
  } while(0)

  ISSUE1(0);
  for (int kc = 0; kc < NKC; kc++){
    if (kc + 1 < NKC){ ISSUE1(kc+1); CP_WAIT1(); }
    else             { CP_WAIT0(); }
    __syncthreads();
    mma_chunk1(sb0 + (kc&1)*BUF1, aoff, boff, F);
    __syncthreads();
  }
  #undef ISSUE1
}

// =====================================================================
__global__ __launch_bounds__(256) void k_sort(const int* __restrict__ choice){
  __shared__ int offs[NCLST];
  __shared__ int hist[NCLST];
  const int t = threadIdx.x, b = blockIdx.x;
  const int base = b*NPTS;
  if (t < NCLST){ hist[t] = 0; }
  __syncthreads();
  for (int i=t; i<NPTS; i+=256) atomicAdd(&hist[choice[base+i]], 1);
  __syncthreads();
  if (t == 0){
    int s = 0;
    for (int c=0;c<NCLST;c++){ offs[c] = s; s += hist[c]; }
  }
  __syncthreads();
  for (int i=t; i<NPTS; i+=256){
    int c = choice[base+i];
    int pos = atomicAdd(&offs[c], 1);
    g_perm[base+pos] = base + i;
    g_chs [base+pos] = c;
  }
}

__global__ void k_prep(
    const float* __restrict__ w1, const float* __restrict__ b1,
    const float* __restrict__ bg1, const float* __restrict__ bb1,
    const float* __restrict__ bm1, const float* __restrict__ bv1,
    const float* __restrict__ w2,
    const float* __restrict__ w3, const float* __restrict__ w4,
    const float* __restrict__ b3,
    const float* __restrict__ bg2, const float* __restrict__ bb2,
    const float* __restrict__ bm2, const float* __restrict__ bv2)
{
  int i = blockIdx.x*blockDim.x + threadIdx.x;
  if (i < NFG*C2) g_fg[i] = ENC_NEG_INF;
  if (i < NFG*CO) g_om[i] = ENC_NEG_INF;
  if (i < CF*CF){ uint16_t h,l; split2h(w3[i],h,l); g_w3_h[i]=h; g_w3_l[i]=l; }
  int j = i - CF*CF;
  if (j >= 0 && j < CO*CF)
    g_w4_h[j] = __half_as_ushort(__float2half_rn(w4[j]));
  int k = i - CF*CF - CO*CF;
  if (k >= 0 && k < C2*C1){ uint16_t h,l; split2h(w2[k],h,l); g_w2_h[k]=h; g_w2_l[k]=l; }
  int m = i - CF*CF - CO*CF - C2*C1;
  if (m >= 0 && m < CF){
    float s = bg2[m] * rsqrtf(bv2[m] + 1e-5f);
    g_s2[m] = s;
    g_t2[m] = bb2[m] + (b3[m] - bm2[m]) * s;
  }
  int q = i - CF*CF - CO*CF - C2*C1 - CF;
  if (q >= 0 && q < C1){
    float s = bg1[q] * rsqrtf(bv1[q] + 1e-5f);
    g_w1f[q*4+0] = w1[q*3+0]*s;
    g_w1f[q*4+1] = w1[q*3+1]*s;
    g_w1f[q*4+2] = w1[q*3+2]*s;
    g_w1f[q*4+3] = (b1[q] - bm1[q])*s + bb1[q];
  }
}

// =====================================================================
// Stage 1 (fp16 2-term, inline h): feat fp16 + segment fg max. grid (2048,2)
// =====================================================================
__global__ __launch_bounds__(256) void k_stage1(
    const float* __restrict__ xyz, const float* __restrict__ b2)
{
  extern __shared__ char smem[];
  __shared__ float sx[128][3];
  __shared__ int   scl[128];
  __shared__ int   sperm[128];
  __shared__ __align__(16) float sw1[C1*4];

  const int t = threadIdx.x, lane = t & 31, wid = t >> 5;
  const int p0 = blockIdx.x*128, bb = blockIdx.x >> 6;
  const int ch0 = blockIdx.y*128;

  for (int i=t; i<128; i+=256){ scl[i] = g_chs[p0+i]; sperm[i] = g_perm[p0+i]; }
  for (int i=t; i<C1*4; i+=256) sw1[i] = g_w1f[i];
  __syncthreads();
  for (int i=t; i<128*3; i+=256) sx[i/3][i%3] = xyz[(size_t)sperm[i/3]*3 + (i%3)];
  __syncthreads();

  const uint32_t sb = smem_u32(smem);
  uint16_t* pA = (uint16_t*)smem;

  const int wm = (wid & 1)*64, wn = (wid >> 1)*32;
  const uint32_t aoff = (uint32_t)(wm + (lane & 15))*ROWB + ((lane >> 4) & 1)*16;
  const uint32_t boff = (uint32_t)(wn + (lane & 7) + ((lane >> 4) & 1)*8)*ROWB
                      + ((lane >> 3) & 1)*16;

  Frag F;
  #pragma unroll
  for (int mi=0;mi<4;mi++)
    #pragma unroll
    for (int ni=0;ni<4;ni++)
      #pragma unroll
      for (int c=0;c<4;c++) F.acc[mi][ni][c] = 0.f;

  for (int kc=0; kc<4; kc++){
    for (int idx=t; idx<512; idx+=256){
      int row = idx >> 2, c = idx & 3;
      size_t off = (size_t)(ch0+row)*C1 + kc*KC + c*8;
      uint32_t so = (uint32_t)row*ROWB + c*16;
      cp16(sb + PLANE + so,   g_w2_h + off);
      cp16(sb + 2*PLANE + so, g_w2_l + off);
    }
    CP_COMMIT();
    for (int idx=t; idx<4096; idx+=256){
      int row = idx >> 5, kp = idx & 31;
      int k = kc*KC + kp;
      float4 wf = *(const float4*)(sw1 + 4*k);
      float h = fmaf(sx[row][0], wf.x, fmaf(sx[row][1], wf.y, fmaf(sx[row][2], wf.z, wf.w)));
      h = fmaxf(h, 0.f);
      pA[(uint32_t)row*(ROWB/2) + kp] = __half_as_ushort(__float2half_rn(h));
    }
    CP_WAIT0();
    __syncthreads();
    mma_chunk3(sb, aoff, boff, F);
    __syncthreads();
  }

  float* Sv = (float*)smem;
  const int r0 = lane >> 2, cp = (lane & 3)*2;
  #pragma unroll
  for (int mi=0;mi<4;mi++){
    int pa = wm + mi*16 + r0;
    size_t ga = (size_t)(p0 + pa), gb = ga + 8;
    #pragma unroll
    for (int ni=0;ni<4;ni++){
      int chl = wn + ni*8 + cp;
      int ch  = ch0 + chl;
      float b0 = b2[ch], b1v = b2[ch+1];
      float x0 = __half2float(__float2half_rn(F.acc[mi][ni][0] + b0));
      float x1 = __half2float(__float2half_rn(F.acc[mi][ni][1] + b1v));
      float y0 = __half2float(__float2half_rn(F.acc[mi][ni][2] + b0));
      float y1 = __half2float(__float2half_rn(F.acc[mi][ni][3] + b1v));
      uint32_t px = (uint32_t)__half_as_ushort(__float2half_rn(x0))
                  | ((uint32_t)__half_as_ushort(__float2half_rn(x1)) << 16);
      uint32_t py = (uint32_t)__half_as_ushort(__float2half_rn(y0))
                  | ((uint32_t)__half_as_ushort(__float2half_rn(y1)) << 16);
      *(uint32_t*)(g_featf + ga*C2 + ch) = px;
      *(uint32_t*)(g_featf + gb*C2 + ch) = py;
      *(float2*)&Sv[(size_t)pa*SVSTR + chl]     = make_float2(x0, x1);
      *(float2*)&Sv[(size_t)(pa+8)*SVSTR + chl] = make_float2(y0, y1);
    }
  }
  __syncthreads();

  {
    const int ch = t & 127, half = t >> 7;
    int r = half*64;
    int cprev = scl[r];
    float run = __int_as_float(0xff800000);
    unsigned* fgb = &g_fg[(size_t)bb*NCLST*C2 + ch0 + ch];
    for (int i=0;i<64;i++,r++){
      int c = scl[r];
      if (c != cprev){
        atomicMax(&fgb[(size_t)cprev*C2], enc(run));
        run = __int_as_float(0xff800000);
        cprev = c;
      }
      run = fmaxf(run, Sv[(size_t)r*SVSTR + ch]);
    }
    atomicMax(&fgb[(size_t)cprev*C2], enc(run));
  }
}

__global__ void k_fg_split(){
  int i = blockIdx.x*blockDim.x + threadIdx.x;
  if (i < NFG*C2)
    g_fgf[i] = __half_as_ushort(__float2half_rn(dec(g_fg[i])));
}

// =====================================================================
// Cluster GEMM (fp16 2-term): G = fg @ w3[:, :256]^T   grid (16, 4)
// =====================================================================
__global__ __launch_bounds__(256) void k_gemmC()
{
  extern __shared__ char smem[];
  const int t = threadIdx.x, lane = t & 31, wid = t >> 5;
  const int r0b = blockIdx.x*128;
  const int ch0 = blockIdx.y*128;

  Frag F;
  gemm_core3(smem_u32(smem), r0b, g_fgf, C2, ch0, g_w3_h, g_w3_l, CF, 0, C2/KC, F);

  const int wm = (wid & 1)*64, wn = (wid >> 1)*32;
  const int r0 = lane >> 2, cp = (lane & 3)*2;
  #pragma unroll
  for (int mi=0;mi<4;mi++){
    size_t ga = (size_t)(r0b + wm + mi*16 + r0), gb = ga + 8;
    #pragma unroll
    for (int ni=0;ni<4;ni++){
      int ch = ch0 + wn + ni*8 + cp;
      *(float2*)(g_G + ga*CF + ch) = make_float2(F.acc[mi][ni][0], F.acc[mi][ni][1]);
      *(float2*)(g_G + gb*CF + ch) = make_float2(F.acc[mi][ni][2], F.acc[mi][ni][3]);
    }
  }
}

// =====================================================================
// GEMM2 (fp16 1-term, K=256): h2 = relu(bn2(feat @ w3h[:,256:]^T + G))
// grid (2048, 4)
// =====================================================================
__global__ __launch_bounds__(256) void k_gemm2()
{
  extern __shared__ char smem[];
  __shared__ int scl[128];
  const int t = threadIdx.x, lane = t & 31, wid = t >> 5;
  const int p0 = blockIdx.x*128, bb = blockIdx.x >> 6;
  const int ch0 = blockIdx.y*128;

  for (int i=t; i<128; i+=256) scl[i] = g_chs[p0+i];
  __syncthreads();

  Frag F;
  gemm_core1(smem_u32(smem), p0, g_featf, C2, ch0, g_w3_h, CF, C2, C2/KC, F);

  const int wm = (wid & 1)*64, wn = (wid >> 1)*32;
  const int r0 = lane >> 2, cp = (lane & 3)*2;
  #pragma unroll
  for (int mi=0;mi<4;mi++){
    int pa = wm + mi*16 + r0;
    size_t ga = (size_t)(p0 + pa), gb = ga + 8;
    const float* Ga = &g_G[(size_t)(bb*NCLST + scl[pa])*CF];
    const float* Gb = &g_G[(size_t)(bb*NCLST + scl[pa+8])*CF];
    #pragma unroll
    for (int ni=0;ni<4;ni++){
      int ch = ch0 + wn + ni*8 + cp;
      float s0 = g_s2[ch], s1 = g_s2[ch+1];
      float t0 = g_t2[ch], t1 = g_t2[ch+1];
      float2 gva = *(const float2*)(Ga + ch);
      float2 gvb = *(const float2*)(Gb + ch);
      float x0 = fmaxf(fmaf(F.acc[mi][ni][0] + gva.x, s0, t0), 0.f);
      float x1 = fmaxf(fmaf(F.acc[mi][ni][1] + gva.y, s1, t1), 0.f);
      float y0 = fmaxf(fmaf(F.acc[mi][ni][2] + gvb.x, s0, t0), 0.f);
      float y1 = fmaxf(fmaf(F.acc[mi][ni][3] + gvb.y, s1, t1), 0.f);
      uint32_t px = (uint32_t)__half_as_ushort(__float2half_rn(x0))
                  | ((uint32_t)__half_as_ushort(__float2half_rn(x1)) << 16);
      uint32_t py = (uint32_t)__half_as_ushort(__float2half_rn(y0))
                  | ((uint32_t)__half_as_ushort(__float2half_rn(y1)) << 16);
      *(uint32_t*)(g_h2f + ga*CF + ch) = px;
      *(uint32_t*)(g_h2f + gb*CF + ch) = py;
    }
  }
}

// =====================================================================
// GEMM3 (fp16 1-term, K=512): out = h2 @ w4h^T + b4 -> segment max
// grid (2048, 3)
// =====================================================================
__global__ __launch_bounds__(256) void k_gemm3(const float* __restrict__ b4)
{
  extern __shared__ char smem[];
  __shared__ int scl[128];
  const int t = threadIdx.x, lane = t & 31, wid = t >> 5;
  const int p0 = blockIdx.x*128, bb = blockIdx.x >> 6;
  const int ch0 = blockIdx.y*128;

  for (int i=t; i<128; i+=256) scl[i] = g_chs[p0+i];
  __syncthreads();

  Frag F;
  gemm_core1(smem_u32(smem), p0, g_h2f, CF, ch0, g_w4_h, CF, 0, CF/KC, F);

  float* Sv = (float*)smem;
  const int wm = (wid & 1)*64, wn = (wid >> 1)*32;
  const int r0 = lane >> 2, cp = (lane & 3)*2;
  #pragma unroll
  for (int mi=0;mi<4;mi++){
    int pa = wm + mi*16 + r0;
    #pragma unroll
    for (int ni=0;ni<4;ni++){
      int chl = wn + ni*8 + cp;
      int ch  = ch0 + chl;
      float b0 = b4[ch], b1 = b4[ch+1];
      *(float2*)&Sv[(size_t)pa*SVSTR + chl] =
          make_float2(F.acc[mi][ni][0] + b0, F.acc[mi][ni][1] + b1);
      *(float2*)&Sv[(size_t)(pa+8)*SVSTR + chl] =
          make_float2(F.acc[mi][ni][2] + b0, F.acc[mi][ni][3] + b1);
    }
  }
  __syncthreads();

  {
    const int ch = t & 127, half = t >> 7;
    int r = half*64;
    int cprev = scl[r];
    float run = __int_as_float(0xff800000);
    unsigned* omb = &g_om[(size_t)bb*NCLST*CO + ch0 + ch];
    for (int i=0;i<64;i++,r++){
      int c = scl[r];
      if (c != cprev){
        atomicMax(&omb[(size_t)cprev*CO], enc(run));
        run = __int_as_float(0xff800000);
        cprev = c;
      }
      run = fmaxf(run, Sv[(size_t)r*SVSTR + ch]);
    }
    atomicMax(&omb[(size_t)cprev*CO], enc(run));
  }
}

__global__ void k_final(float* __restrict__ out){
  int i = blockIdx.x*blockDim.x + threadIdx.x;
  if (i < NFG*CO) out[i] = dec(g_om[i]);
}

// =====================================================================
extern "C" void kernel_launch(void* const* d_in, const int* in_sizes, int n_in,
                              void* d_out, int out_size)
{
  const float* xyz    = (const float*)d_in[0];
  const int*   choice = (const int*)  d_in[1];
  const float* w1  = (const float*)d_in[2];
  const float* b1  = (const float*)d_in[3];
  const float* g1  = (const float*)d_in[4];
  const float* bb1 = (const float*)d_in[5];
  const float* m1  = (const float*)d_in[6];
  const float* v1  = (const float*)d_in[7];
  const float* w2  = (const float*)d_in[8];
  const float* b2  = (const float*)d_in[9];
  const float* w3  = (const float*)d_in[10];
  const float* b3  = (const float*)d_in[11];
  const float* g2  = (const float*)d_in[12];
  const float* bb2 = (const float*)d_in[13];
  const float* m2  = (const float*)d_in[14];
  const float* v2  = (const float*)d_in[15];
  const float* w4  = (const float*)d_in[16];
  const float* b4  = (const float*)d_in[17];

  size_t smem1  = SVB;       // 66560
  size_t smemC  = 2*BUF3;    // 61440
  size_t smem2  = 2*BUF1;    // 40960
  size_t smem3s = SVB;       // 66560 (2*BUF1=40960 and Sv both fit)
  cudaFuncSetAttribute(k_stage1, cudaFuncAttributeMaxDynamicSharedMemorySize, (int)smem1);
  cudaFuncSetAttribute(k_gemmC,  cudaFuncAttributeMaxDynamicSharedMemorySize, (int)smemC);
  cudaFuncSetAttribute(k_gemm2,  cudaFuncAttributeMaxDynamicSharedMemorySize, (int)smem2);
  cudaFuncSetAttribute(k_gemm3,  cudaFuncAttributeMaxDynamicSharedMemorySize, (int)smem3s);

  int nprep = NFG*CO;

  k_sort    <<<BATCH, 256>>>(choice);
  k_prep    <<<(nprep+255)/256, 256>>>(w1,b1,g1,bb1,m1,v1,w2, w3,w4,b3,g2,bb2,m2,v2);
  {
    dim3 g1d(PTOT/128, C2/128);   // (2048, 2)
    k_stage1<<<g1d, 256, smem1>>>(xyz, b2);
  }
  k_fg_split<<<(NFG*C2+255)/256, 256>>>();
  {
    dim3 gcd(NFG/128, CF/128);    // (16, 4)
    k_gemmC<<<gcd, 256, smemC>>>();
    dim3 g2d(PTOT/128, CF/128);   // (2048, 4)
    k_gemm2<<<g2d, 256, smem2>>>();
    dim3 g3d(PTOT/128, CO/128);   // (2048, 3)
    k_gemm3<<<g3d, 256, smem3s>>>(b4);
  }
  k_final   <<<(NFG*CO+255)/256, 256>>>((float*)d_out);
}

// round 17
// speedup vs baseline: 2.3007x; 1.1443x over previous
#include <cuda_runtime.h>
#include <cuda_bf16.h>
#include <cuda_fp16.h>
#include <stdint.h>

#define BATCH 32
#define NPTS  8192
#define NCLST 64
#define C1    128
#define C2    256
#define CF    512
#define CO    384
#define PTOT  (BATCH*NPTS)
#define NFG   (BATCH*NCLST)
#define ENC_NEG_INF 0x007FFFFFu

// KC=32 geometry (stage1 / gemmC)
#define ROWB   80
#define PLANE  (128*ROWB)       // 10240 B
#define BUF3   (3*PLANE)        // 30720 B (2-term: A,Bh,Bl)
#define KC     32
// KC=64 geometry (gemm2 / gemm3, 1-term)
#define ROWB64  144
#define PLANE64 (128*ROWB64)    // 18432 B
#define BUF64B  (2*PLANE64)     // 36864 B
#define SVSTR  130
#define SVB    (128*SVSTR*4)    // 66560 B

// ---------------- scratch ----------------
__device__ unsigned g_fg[NFG*C2];
__device__ unsigned g_om[NFG*CO];
__device__ int g_perm[PTOT];
__device__ int g_chs[PTOT];
__device__ __align__(16) uint16_t g_featf[(size_t)PTOT*C2];  // feat fp16
__device__ __align__(16) uint16_t g_fgf[NFG*C2];             // fg fp16
__device__ __align__(16) uint16_t g_h2f[(size_t)PTOT*CF];    // h2 fp16
__device__ __align__(16) uint16_t g_w2_h[C2*C1];                  // fp16 single
__device__ __align__(16) uint16_t g_w3_h[CF*CF], g_w3_l[CF*CF];   // fp16 split (lo: gemmC only)
__device__ __align__(16) uint16_t g_w4_h[CO*CF];                  // fp16 single
__device__ float g_G[(size_t)NFG*CF];
__device__ float g_s2[CF], g_t2[CF];
__device__ __align__(16) float g_w1f[C1*4];

// ---------------- helpers ----------------
__device__ __forceinline__ unsigned enc(float f){
  unsigned u = __float_as_uint(f);
  return (u & 0x80000000u) ? ~u : (u | 0x80000000u);
}
__device__ __forceinline__ float dec(unsigned u){
  u = (u & 0x80000000u) ? (u & 0x7FFFFFFFu) : ~u;
  return __uint_as_float(u);
}
__device__ __forceinline__ void split2h(float v, uint16_t& h, uint16_t& l){
  __half hh = __float2half_rn(v);
  float r = v - __half2float(hh);
  if (!(r == r)) r = 0.f;
  h = __half_as_ushort(hh);
  l = __half_as_ushort(__float2half_rn(r));
}
__device__ __forceinline__ uint32_t smem_u32(const void* p){
  uint32_t a;
  asm("{ .reg .u64 t; cvta.to.shared.u64 t, %1; cvt.u32.u64 %0, t; }" : "=r"(a) : "l"(p));
  return a;
}
__device__ __forceinline__ void cp16(uint32_t dst, const void* src){
  asm volatile("cp.async.cg.shared.global [%0], [%1], 16;" :: "r"(dst), "l"(src));
}
#define CP_COMMIT() asm volatile("cp.async.commit_group;" ::: "memory")
#define CP_WAIT1()  asm volatile("cp.async.wait_group 1;"  ::: "memory")
#define CP_WAIT0()  asm volatile("cp.async.wait_group 0;"  ::: "memory")

__device__ __forceinline__ void ldsm4(uint32_t* r, uint32_t addr){
  asm volatile("ldmatrix.sync.aligned.m8n8.x4.shared.b16 {%0,%1,%2,%3}, [%4];"
    : "=r"(r[0]),"=r"(r[1]),"=r"(r[2]),"=r"(r[3]) : "r"(addr));
}
__device__ __forceinline__ void mma16816h(float* c, const uint32_t* a, const uint32_t* b){
  asm volatile("mma.sync.aligned.m16n8k16.row.col.f32.f16.f16.f32 "
    "{%0,%1,%2,%3}, {%4,%5,%6,%7}, {%8,%9}, {%0,%1,%2,%3};"
    : "+f"(c[0]),"+f"(c[1]),"+f"(c[2]),"+f"(c[3])
    : "r"(a[0]),"r"(a[1]),"r"(a[2]),"r"(a[3]), "r"(b[0]),"r"(b[1]));
}

struct Frag { float acc[4][4][4]; };

// fp16 2-term chunk, KC=32 planes (gemmC)
__device__ __forceinline__ void mma_chunk3(uint32_t sb, uint32_t aoff, uint32_t boff, Frag& F){
  const uint32_t aA = sb, aBh = sb + PLANE, aBl = sb + 2*PLANE;
  #pragma unroll
  for (int ks = 0; ks < 2; ks++){
    const uint32_t kb = ks * 32;
    uint32_t a[4][4], bH[2][4], bL[2][4];
    #pragma unroll
    for (int mi=0;mi<4;mi++) ldsm4(a[mi],  aA  + aoff + mi*(16*ROWB) + kb);
    #pragma unroll
    for (int nj=0;nj<2;nj++) ldsm4(bH[nj], aBh + boff + nj*(16*ROWB) + kb);
    #pragma unroll
    for (int mi=0;mi<4;mi++)
      #pragma unroll
      for (int nj=0;nj<2;nj++){
        mma16816h(F.acc[mi][nj*2+0], a[mi], &bH[nj][0]);
        mma16816h(F.acc[mi][nj*2+1], a[mi], &bH[nj][2]);
      }
    #pragma unroll
    for (int nj=0;nj<2;nj++) ldsm4(bL[nj], aBl + boff + nj*(16*ROWB) + kb);
    #pragma unroll
    for (int mi=0;mi<4;mi++)
      #pragma unroll
      for (int nj=0;nj<2;nj++){
        mma16816h(F.acc[mi][nj*2+0], a[mi], &bL[nj][0]);
        mma16816h(F.acc[mi][nj*2+1], a[mi], &bL[nj][2]);
      }
  }
}

// fp16 1-term chunk, KC=32 planes (stage1)
__device__ __forceinline__ void mma_chunk1(uint32_t sb, uint32_t aoff, uint32_t boff, Frag& F){
  const uint32_t aA = sb, aB = sb + PLANE;
  #pragma unroll
  for (int ks = 0; ks < 2; ks++){
    const uint32_t kb = ks * 32;
    uint32_t a[4][4], b[2][4];
    #pragma unroll
    for (int mi=0;mi<4;mi++) ldsm4(a[mi], aA + aoff + mi*(16*ROWB) + kb);
    #pragma unroll
    for (int nj=0;nj<2;nj++) ldsm4(b[nj], aB + boff + nj*(16*ROWB) + kb);
    #pragma unroll
    for (int mi=0;mi<4;mi++)
      #pragma unroll
      for (int nj=0;nj<2;nj++){
        mma16816h(F.acc[mi][nj*2+0], a[mi], &b[nj][0]);
        mma16816h(F.acc[mi][nj*2+1], a[mi], &b[nj][2]);
      }
  }
}

// fp16 1-term chunk, KC=64 planes (gemm2/gemm3)
__device__ __forceinline__ void mma_chunk1_64(uint32_t sb, uint32_t aoff, uint32_t boff, Frag& F){
  const uint32_t aA = sb, aB = sb + PLANE64;
  #pragma unroll
  for (int ks = 0; ks < 4; ks++){
    const uint32_t kb = ks * 32;
    uint32_t a[4][4], b[2][4];
    #pragma unroll
    for (int mi=0;mi<4;mi++) ldsm4(a[mi], aA + aoff + mi*(16*ROWB64) + kb);
    #pragma unroll
    for (int nj=0;nj<2;nj++) ldsm4(b[nj], aB + boff + nj*(16*ROWB64) + kb);
    #pragma unroll
    for (int mi=0;mi<4;mi++)
      #pragma unroll
      for (int nj=0;nj<2;nj++){
        mma16816h(F.acc[mi][nj*2+0], a[mi], &b[nj][0]);
        mma16816h(F.acc[mi][nj*2+1], a[mi], &b[nj][2]);
      }
  }
}

// fp16 2-term double-buffered core, KC=32 (gemmC)
__device__ __forceinline__ void gemm_core3(
    uint32_t sb0, int arow0, const uint16_t* __restrict__ Af, int astride,
    int ch0, const uint16_t* __restrict__ Bh, const uint16_t* __restrict__ Bl,
    int bstride, int bkoff, int NKC, Frag& F)
{
  const int t = threadIdx.x, lane = t & 31, wid = t >> 5;
  const int wm = (wid & 1)*64, wn = (wid >> 1)*32;
  const uint32_t aoff = (uint32_t)(wm + (lane & 15))*ROWB + ((lane >> 4) & 1)*16;
  const uint32_t boff = (uint32_t)(wn + (lane & 7) + ((lane >> 4) & 1)*8)*ROWB
                      + ((lane >> 3) & 1)*16;

  #pragma unroll
  for (int mi=0;mi<4;mi++)
    #pragma unroll
    for (int ni=0;ni<4;ni++)
      #pragma unroll
      for (int c=0;c<4;c++) F.acc[mi][ni][c] = 0.f;

  #define ISSUE3(kc) do { \
    uint32_t sbb = sb0 + ((kc)&1)*BUF3; \
    for (int idx=t; idx<512; idx+=256){ \
      int row = idx >> 2, c = idx & 3; \
      size_t offa = (size_t)(arow0 + row)*astride + (kc)*KC + c*8; \
      size_t offb = (size_t)(ch0 + row)*bstride + bkoff + (kc)*KC + c*8; \
      uint32_t so = (uint32_t)row*ROWB + c*16; \
      cp16(sbb + so,           Af + offa); \
      cp16(sbb + PLANE + so,   Bh + offb); \
      cp16(sbb + 2*PLANE + so, Bl + offb); \
    } \
    CP_COMMIT(); \
  } while(0)

  ISSUE3(0);
  for (int kc = 0; kc < NKC; kc++){
    if (kc + 1 < NKC){ ISSUE3(kc+1); CP_WAIT1(); }
    else             { CP_WAIT0(); }
    __syncthreads();
    mma_chunk3(sb0 + (kc&1)*BUF3, aoff, boff, F);
    __syncthreads();
  }
  #undef ISSUE3
}

// fp16 1-term double-buffered core, KC=64 (gemm2/gemm3)
__device__ __forceinline__ void gemm_core1_64(
    uint32_t sb0, int arow0, const uint16_t* __restrict__ Af, int astride,
    int ch0, const uint16_t* __restrict__ B, int bstride, int bkoff,
    int NKC, Frag& F)
{
  const int t = threadIdx.x, lane = t & 31, wid = t >> 5;
  const int wm = (wid & 1)*64, wn = (wid >> 1)*32;
  const uint32_t aoff = (uint32_t)(wm + (lane & 15))*ROWB64 + ((lane >> 4) & 1)*16;
  const uint32_t boff = (uint32_t)(wn + (lane & 7) + ((lane >> 4) & 1)*8)*ROWB64
                      + ((lane >> 3) & 1)*16;

  #pragma unroll
  for (int mi=0;mi<4;mi++)
    #pragma unroll
    for (int ni=0;ni<4;ni++)
      #pragma unroll
      for (int c=0;c<4;c++) F.acc[mi][ni][c] = 0.f;

  #define ISSUE64(kc) do { \
    uint32_t sbb = sb0 + ((kc)&1)*BUF64B; \
    for (int idx=t; idx<1024; idx+=256){ \
      int row = idx >> 3, c = idx & 7; \
      size_t offa = (size_t)(arow0 + row)*astride + (kc)*64 + c*8; \
      size_t offb = (size_t)(ch0 + row)*bstride + bkoff + (kc)*64 + c*8; \
      uint32_t so = (uint32_t)row*ROWB64 + c*16; \
      cp16(sbb + so,           Af + offa); \
      cp16(sbb + PLANE64 + so, B + offb); \
    } \
    CP_COMMIT(); \
  } while(0)

  ISSUE64(0);
  for (int kc = 0; kc < NKC; kc++){
    if (kc + 1 < NKC){ ISSUE64(kc+1); CP_WAIT1(); }
    else             { CP_WAIT0(); }
    __syncthreads();
    mma_chunk1_64(sb0 + (kc&1)*BUF64B, aoff, boff, F);
    __syncthreads();
  }
  #undef ISSUE64
}

// =====================================================================
__global__ __launch_bounds__(256) void k_sort(const int* __restrict__ choice){
  __shared__ int offs[NCLST];
  __shared__ int hist[NCLST];
  const int t = threadIdx.x, b = blockIdx.x;
  const int base = b*NPTS;
  if (t < NCLST){ hist[t] = 0; }
  __syncthreads();
  for (int i=t; i<NPTS; i+=256) atomicAdd(&hist[choice[base+i]], 1);
  __syncthreads();
  if (t == 0){
    int s = 0;
    for (int c=0;c<NCLST;c++){ offs[c] = s; s += hist[c]; }
  }
  __syncthreads();
  for (int i=t; i<NPTS; i+=256){
    int c = choice[base+i];
    int pos = atomicAdd(&offs[c], 1);
    g_perm[base+pos] = base + i;
    g_chs [base+pos] = c;
  }
}

__global__ void k_prep(
    const float* __restrict__ w1, const float* __restrict__ b1,
    const float* __restrict__ bg1, const float* __restrict__ bb1,
    const float* __restrict__ bm1, const float* __restrict__ bv1,
    const float* __restrict__ w2,
    const float* __restrict__ w3, const float* __restrict__ w4,
    const float* __restrict__ b3,
    const float* __restrict__ bg2, const float* __restrict__ bb2,
    const float* __restrict__ bm2, const float* __restrict__ bv2)
{
  int i = blockIdx.x*blockDim.x + threadIdx.x;
  if (i < NFG*C2) g_fg[i] = ENC_NEG_INF;
  if (i < NFG*CO) g_om[i] = ENC_NEG_INF;
  if (i < CF*CF){ uint16_t h,l; split2h(w3[i],h,l); g_w3_h[i]=h; g_w3_l[i]=l; }
  int j = i - CF*CF;
  if (j >= 0 && j < CO*CF)
    g_w4_h[j] = __half_as_ushort(__float2half_rn(w4[j]));
  int k = i - CF*CF - CO*CF;
  if (k >= 0 && k < C2*C1)
    g_w2_h[k] = __half_as_ushort(__float2half_rn(w2[k]));
  int m = i - CF*CF - CO*CF - C2*C1;
  if (m >= 0 && m < CF){
    float s = bg2[m] * rsqrtf(bv2[m] + 1e-5f);
    g_s2[m] = s;
    g_t2[m] = bb2[m] + (b3[m] - bm2[m]) * s;
  }
  int q = i - CF*CF - CO*CF - C2*C1 - CF;
  if (q >= 0 && q < C1){
    float s = bg1[q] * rsqrtf(bv1[q] + 1e-5f);
    g_w1f[q*4+0] = w1[q*3+0]*s;
    g_w1f[q*4+1] = w1[q*3+1]*s;
    g_w1f[q*4+2] = w1[q*3+2]*s;
    g_w1f[q*4+3] = (b1[q] - bm1[q])*s + bb1[q];
  }
}

// =====================================================================
// Stage 1 (fp16 1-term, inline h): feat fp16 + segment fg max. grid (2048,2)
// =====================================================================
__global__ __launch_bounds__(256) void k_stage1(
    const float* __restrict__ xyz, const float* __restrict__ b2)
{
  extern __shared__ char smem[];
  __shared__ float sx[128][3];
  __shared__ int   scl[128];
  __shared__ int   sperm[128];
  __shared__ __align__(16) float sw1[C1*4];

  const int t = threadIdx.x, lane = t & 31, wid = t >> 5;
  const int p0 = blockIdx.x*128, bb = blockIdx.x >> 6;
  const int ch0 = blockIdx.y*128;

  for (int i=t; i<128; i+=256){ scl[i] = g_chs[p0+i]; sperm[i] = g_perm[p0+i]; }
  for (int i=t; i<C1*4; i+=256) sw1[i] = g_w1f[i];
  __syncthreads();
  for (int i=t; i<128*3; i+=256) sx[i/3][i%3] = xyz[(size_t)sperm[i/3]*3 + (i%3)];
  __syncthreads();

  const uint32_t sb = smem_u32(smem);
  uint16_t* pA = (uint16_t*)smem;

  const int wm = (wid & 1)*64, wn = (wid >> 1)*32;
  const uint32_t aoff = (uint32_t)(wm + (lane & 15))*ROWB + ((lane >> 4) & 1)*16;
  const uint32_t boff = (uint32_t)(wn + (lane & 7) + ((lane >> 4) & 1)*8)*ROWB
                      + ((lane >> 3) & 1)*16;

  Frag F;
  #pragma unroll
  for (int mi=0;mi<4;mi++)
    #pragma unroll
    for (int ni=0;ni<4;ni++)
      #pragma unroll
      for (int c=0;c<4;c++) F.acc[mi][ni][c] = 0.f;

  for (int kc=0; kc<4; kc++){
    for (int idx=t; idx<512; idx+=256){
      int row = idx >> 2, c = idx & 3;
      size_t off = (size_t)(ch0+row)*C1 + kc*KC + c*8;
      uint32_t so = (uint32_t)row*ROWB + c*16;
      cp16(sb + PLANE + so, g_w2_h + off);
    }
    CP_COMMIT();
    for (int idx=t; idx<4096; idx+=256){
      int row = idx >> 5, kp = idx & 31;
      int k = kc*KC + kp;
      float4 wf = *(const float4*)(sw1 + 4*k);
      float h = fmaf(sx[row][0], wf.x, fmaf(sx[row][1], wf.y, fmaf(sx[row][2], wf.z, wf.w)));
      h = fmaxf(h, 0.f);
      pA[(uint32_t)row*(ROWB/2) + kp] = __half_as_ushort(__float2half_rn(h));
    }
    CP_WAIT0();
    __syncthreads();
    mma_chunk1(sb, aoff, boff, F);
    __syncthreads();
  }

  float* Sv = (float*)smem;
  const int r0 = lane >> 2, cp = (lane & 3)*2;
  #pragma unroll
  for (int mi=0;mi<4;mi++){
    int pa = wm + mi*16 + r0;
    size_t ga = (size_t)(p0 + pa), gb = ga + 8;
    #pragma unroll
    for (int ni=0;ni<4;ni++){
      int chl = wn + ni*8 + cp;
      int ch  = ch0 + chl;
      float b0 = b2[ch], b1v = b2[ch+1];
      float x0 = __half2float(__float2half_rn(F.acc[mi][ni][0] + b0));
      float x1 = __half2float(__float2half_rn(F.acc[mi][ni][1] + b1v));
      float y0 = __half2float(__float2half_rn(F.acc[mi][ni][2] + b0));
      float y1 = __half2float(__float2half_rn(F.acc[mi][ni][3] + b1v));
      uint32_t px = (uint32_t)__half_as_ushort(__float2half_rn(x0))
                  | ((uint32_t)__half_as_ushort(__float2half_rn(x1)) << 16);
      uint32_t py = (uint32_t)__half_as_ushort(__float2half_rn(y0))
                  | ((uint32_t)__half_as_ushort(__float2half_rn(y1)) << 16);
      *(uint32_t*)(g_featf + ga*C2 + ch) = px;
      *(uint32_t*)(g_featf + gb*C2 + ch) = py;
      *(float2*)&Sv[(size_t)pa*SVSTR + chl]     = make_float2(x0, x1);
      *(float2*)&Sv[(size_t)(pa+8)*SVSTR + chl] = make_float2(y0, y1);
    }
  }
  __syncthreads();

  {
    const int ch = t & 127, half = t >> 7;
    int r = half*64;
    int cprev = scl[r];
    float run = __int_as_float(0xff800000);
    unsigned* fgb = &g_fg[(size_t)bb*NCLST*C2 + ch0 + ch];
    for (int i=0;i<64;i++,r++){
      int c = scl[r];
      if (c != cprev){
        atomicMax(&fgb[(size_t)cprev*C2], enc(run));
        run = __int_as_float(0xff800000);
        cprev = c;
      }
      run = fmaxf(run, Sv[(size_t)r*SVSTR + ch]);
    }
    atomicMax(&fgb[(size_t)cprev*C2], enc(run));
  }
}

__global__ void k_fg_split(){
  int i = blockIdx.x*blockDim.x + threadIdx.x;
  if (i < NFG*C2)
    g_fgf[i] = __half_as_ushort(__float2half_rn(dec(g_fg[i])));
}

// =====================================================================
// Cluster GEMM (fp16 2-term): G = fg @ w3[:, :256]^T   grid (16, 4)
// =====================================================================
__global__ __launch_bounds__(256) void k_gemmC()
{
  extern __shared__ char smem[];
  const int t = threadIdx.x, lane = t & 31, wid = t >> 5;
  const int r0b = blockIdx.x*128;
  const int ch0 = blockIdx.y*128;

  Frag F;
  gemm_core3(smem_u32(smem), r0b, g_fgf, C2, ch0, g_w3_h, g_w3_l, CF, 0, C2/KC, F);

  const int wm = (wid & 1)*64, wn = (wid >> 1)*32;
  const int r0 = lane >> 2, cp = (lane & 3)*2;
  #pragma unroll
  for (int mi=0;mi<4;mi++){
    size_t ga = (size_t)(r0b + wm + mi*16 + r0), gb = ga + 8;
    #pragma unroll
    for (int ni=0;ni<4;ni++){
      int ch = ch0 + wn + ni*8 + cp;
      *(float2*)(g_G + ga*CF + ch) = make_float2(F.acc[mi][ni][0], F.acc[mi][ni][1]);
      *(float2*)(g_G + gb*CF + ch) = make_float2(F.acc[mi][ni][2], F.acc[mi][ni][3]);
    }
  }
}

// =====================================================================
// GEMM2 (fp16 1-term, KC=64, K=256): h2 = relu(bn2(feat@w3h[:,256:]^T + G))
// grid (2048, 4)
// =====================================================================
__global__ __launch_bounds__(256) void k_gemm2()
{
  extern __shared__ char smem[];
  __shared__ int scl[128];
  const int t = threadIdx.x, lane = t & 31, wid = t >> 5;
  const int p0 = blockIdx.x*128, bb = blockIdx.x >> 6;
  const int ch0 = blockIdx.y*128;

  for (int i=t; i<128; i+=256) scl[i] = g_chs[p0+i];
  __syncthreads();

  Frag F;
  gemm_core1_64(smem_u32(smem), p0, g_featf, C2, ch0, g_w3_h, CF, C2, C2/64, F);

  const int wm = (wid & 1)*64, wn = (wid >> 1)*32;
  const int r0 = lane >> 2, cp = (lane & 3)*2;
  #pragma unroll
  for (int mi=0;mi<4;mi++){
    int pa = wm + mi*16 + r0;
    size_t ga = (size_t)(p0 + pa), gb = ga + 8;
    const float* Ga = &g_G[(size_t)(bb*NCLST + scl[pa])*CF];
    const float* Gb = &g_G[(size_t)(bb*NCLST + scl[pa+8])*CF];
    #pragma unroll
    for (int ni=0;ni<4;ni++){
      int ch = ch0 + wn + ni*8 + cp;
      float s0 = g_s2[ch], s1 = g_s2[ch+1];
      float t0 = g_t2[ch], t1 = g_t2[ch+1];
      float2 gva = *(const float2*)(Ga + ch);
      float2 gvb = *(const float2*)(Gb + ch);
      float x0 = fmaxf(fmaf(F.acc[mi][ni][0] + gva.x, s0, t0), 0.f);
      float x1 = fmaxf(fmaf(F.acc[mi][ni][1] + gva.y, s1, t1), 0.f);
      float y0 = fmaxf(fmaf(F.acc[mi][ni][2] + gvb.x, s0, t0), 0.f);
      float y1 = fmaxf(fmaf(F.acc[mi][ni][3] + gvb.y, s1, t1), 0.f);
      uint32_t px = (uint32_t)__half_as_ushort(__float2half_rn(x0))
                  | ((uint32_t)__half_as_ushort(__float2half_rn(x1)) << 16);
      uint32_t py = (uint32_t)__half_as_ushort(__float2half_rn(y0))
                  | ((uint32_t)__half_as_ushort(__float2half_rn(y1)) << 16);
      *(uint32_t*)(g_h2f + ga*CF + ch) = px;
      *(uint32_t*)(g_h2f + gb*CF + ch) = py;
    }
  }
}

// =====================================================================
// GEMM3 (fp16 1-term, KC=64, K=512): out = h2 @ w4h^T + b4 -> segment max
// grid (2048, 3)
// =====================================================================
__global__ __launch_bounds__(256) void k_gemm3(const float* __restrict__ b4)
{
  extern __shared__ char smem[];
  __shared__ int scl[128];
  const int t = threadIdx.x, lane = t & 31, wid = t >> 5;
  const int p0 = blockIdx.x*128, bb = blockIdx.x >> 6;
  const int ch0 = blockIdx.y*128;

  for (int i=t; i<128; i+=256) scl[i] = g_chs[p0+i];
  __syncthreads();

  Frag F;
  gemm_core1_64(smem_u32(smem), p0, g_h2f, CF, ch0, g_w4_h, CF, 0, CF/64, F);

  float* Sv = (float*)smem;
  const int wm = (wid & 1)*64, wn = (wid >> 1)*32;
  const int r0 = lane >> 2, cp = (lane & 3)*2;
  #pragma unroll
  for (int mi=0;mi<4;mi++){
    int pa = wm + mi*16 + r0;
    #pragma unroll
    for (int ni=0;ni<4;ni++){
      int chl = wn + ni*8 + cp;
      int ch  = ch0 + chl;
      float b0 = b4[ch], b1 = b4[ch+1];
      *(float2*)&Sv[(size_t)pa*SVSTR + chl] =
          make_float2(F.acc[mi][ni][0] + b0, F.acc[mi][ni][1] + b1);
      *(float2*)&Sv[(size_t)(pa+8)*SVSTR + chl] =
          make_float2(F.acc[mi][ni][2] + b0, F.acc[mi][ni][3] + b1);
    }
  }
  __syncthreads();

  {
    const int ch = t & 127, half = t >> 7;
    int r = half*64;
    int cprev = scl[r];
    float run = __int_as_float(0xff800000);
    unsigned* omb = &g_om[(size_t)bb*NCLST*CO + ch0 + ch];
    for (int i=0;i<64;i++,r++){
      int c = scl[r];
      if (c != cprev){
        atomicMax(&omb[(size_t)cprev*CO], enc(run));
        run = __int_as_float(0xff800000);
        cprev = c;
      }
      run = fmaxf(run, Sv[(size_t)r*SVSTR + ch]);
    }
    atomicMax(&omb[(size_t)cprev*CO], enc(run));
  }
}

__global__ void k_final(float* __restrict__ out){
  int i = blockIdx.x*blockDim.x + threadIdx.x;
  if (i < NFG*CO) out[i] = dec(g_om[i]);
}

// =====================================================================
extern "C" void kernel_launch(void* const* d_in, const int* in_sizes, int n_in,
                              void* d_out, int out_size)
{
  const float* xyz    = (const float*)d_in[0];
  const int*   choice = (const int*)  d_in[1];
  const float* w1  = (const float*)d_in[2];
  const float* b1  = (const float*)d_in[3];
  const float* g1  = (const float*)d_in[4];
  const float* bb1 = (const float*)d_in[5];
  const float* m1  = (const float*)d_in[6];
  const float* v1  = (const float*)d_in[7];
  const float* w2  = (const float*)d_in[8];
  const float* b2  = (const float*)d_in[9];
  const float* w3  = (const float*)d_in[10];
  const float* b3  = (const float*)d_in[11];
  const float* g2  = (const float*)d_in[12];
  const float* bb2 = (const float*)d_in[13];
  const float* m2  = (const float*)d_in[14];
  const float* v2  = (const float*)d_in[15];
  const float* w4  = (const float*)d_in[16];
  const float* b4  = (const float*)d_in[17];

  size_t smem1  = SVB;        // 66560 (KC32 1-term staging 20480 fits; Sv needs 66560)
  size_t smemC  = 2*BUF3;     // 61440
  size_t smem64 = 2*BUF64B;   // 73728
  cudaFuncSetAttribute(k_stage1, cudaFuncAttributeMaxDynamicSharedMemorySize, (int)smem1);
  cudaFuncSetAttribute(k_gemmC,  cudaFuncAttributeMaxDynamicSharedMemorySize, (int)smemC);
  cudaFuncSetAttribute(k_gemm2,  cudaFuncAttributeMaxDynamicSharedMemorySize, (int)smem64);
  cudaFuncSetAttribute(k_gemm3,  cudaFuncAttributeMaxDynamicSharedMemorySize, (int)smem64);

  int nprep = NFG*CO;

  k_sort    <<<BATCH, 256>>>(choice);
  k_prep    <<<(nprep+255)/256, 256>>>(w1,b1,g1,bb1,m1,v1,w2, w3,w4,b3,g2,bb2,m2,v2);
  {
    dim3 g1d(PTOT/128, C2/128);   // (2048, 2)
    k_stage1<<<g1d, 256, smem1>>>(xyz, b2);
  }
  k_fg_split<<<(NFG*C2+255)/256, 256>>>();
  {
    dim3 gcd(NFG/128, CF/128);    // (16, 4)
    k_gemmC<<<gcd, 256, smemC>>>();
    dim3 g2d(PTOT/128, CF/128);   // (2048, 4)
    k_gemm2<<<g2d, 256, smem64>>>();
    dim3 g3d(PTOT/128, CO/128);   // (2048, 3)
    k_gemm3<<<g3d, 256, smem64>>>(b4);
  }
  k_final   <<<(NFG*CO+255)/256, 256>>>((float*)d_out);
}